// round 12
// baseline (speedup 1.0000x reference)
#include <cuda_runtime.h>
#include <cuda_bf16.h>
#include <math.h>
#include <cstdint>

// ---------------- constants ----------------
#define BATCH   4
#define DIM     64
#define HIDDEN  170
#define C2      340           // 2*HIDDEN
#define HW      65536         // 256*256
#define WIDTH   256
#define PP      8
#define PF      5
#define PARTS   16            // gap partials per (b,c)

// ---------------- scratch (device globals; no allocation allowed) ----------------
__device__ float g_xin [(size_t)BATCH * C2 * HW];      // 356 MB
__device__ float g_feat[(size_t)BATCH * HIDDEN * HW];  // 178 MB (feat, then spatial in-place)
__device__ float g_part[BATCH * HIDDEN * PARTS];
__device__ __nv_bfloat16 g_w1s[2][384][64];            // w_in  split: [hi/lo][o pad][k]
__device__ __nv_bfloat16 g_w2s[2][64][176];            // w_out split: [hi/lo][o][k pad]

// ---------------- helpers ----------------
__device__ __forceinline__ uint32_t smem_u32(const void* p) {
    uint32_t a;
    asm("{ .reg .u64 t; cvta.to.shared.u64 t, %1; cvt.u32.u64 %0, t; }" : "=r"(a) : "l"(p));
    return a;
}
__device__ __forceinline__ uint32_t pack2(float a, float b) {
    uint32_t r;
    asm("cvt.rn.bf16x2.f32 %0, %1, %2;" : "=r"(r) : "f"(b), "f"(a));
    return r;
}
__device__ __forceinline__ void split4(float v0, float v1, float v2, float v3,
                                       uint2& hi, uint2& lo) {
    uint32_t h01 = pack2(v0, v1), h23 = pack2(v2, v3);
    float f0 = __uint_as_float(h01 << 16),  f1 = __uint_as_float(h01 & 0xffff0000u);
    float f2 = __uint_as_float(h23 << 16),  f3 = __uint_as_float(h23 & 0xffff0000u);
    hi = make_uint2(h01, h23);
    lo = make_uint2(pack2(v0 - f0, v1 - f1), pack2(v2 - f2, v3 - f3));
}

__device__ __forceinline__ void mma16816(float d[4], const uint32_t a[4], const uint32_t b[2]) {
    asm volatile(
        "mma.sync.aligned.m16n8k16.row.col.f32.bf16.bf16.f32 "
        "{%0,%1,%2,%3}, {%4,%5,%6,%7}, {%8,%9}, {%0,%1,%2,%3};"
        : "+f"(d[0]), "+f"(d[1]), "+f"(d[2]), "+f"(d[3])
        : "r"(a[0]), "r"(a[1]), "r"(a[2]), "r"(a[3]), "r"(b[0]), "r"(b[1]));
}
__device__ __forceinline__ void ldsm4(uint32_t* r, uint32_t addr) {
    asm volatile("ldmatrix.sync.aligned.m8n8.x4.shared.b16 {%0,%1,%2,%3}, [%4];"
        : "=r"(r[0]), "=r"(r[1]), "=r"(r[2]), "=r"(r[3]) : "r"(addr));
}

// smem tile layout: [ktile][row][16 bf16 = 32B], bit-4 XOR swizzle on (row>>2)&1
__device__ __forceinline__ uint32_t tile_addr(int ktile, int row, int kin2bytes, int kstride) {
    return (uint32_t)(ktile * kstride + ((row * 32 + kin2bytes) ^ (((row >> 2) & 1) << 4)));
}
__device__ __forceinline__ uint32_t row_addr(int row, int byte16) {
    return (uint32_t)((row * 32 + byte16) ^ (((row >> 2) & 1) << 4));
}

// ================= K0: weight split prep =================
__global__ void __launch_bounds__(256) wsplit(const float* __restrict__ w_in,
                                              const float* __restrict__ w_out) {
    int i = blockIdx.x * 256 + threadIdx.x;
    if (i < 384 * 64) {
        int o = i >> 6, k = i & 63;
        float v = (o < C2) ? w_in[o * 64 + k] : 0.f;
        __nv_bfloat16 h = __float2bfloat16(v);
        g_w1s[0][o][k] = h;
        g_w1s[1][o][k] = __float2bfloat16(v - __bfloat162float(h));
    }
    if (i < 64 * 176) {
        int o = i / 176, k = i - o * 176;
        float v = (k < HIDDEN) ? w_out[o * HIDDEN + k] : 0.f;
        __nv_bfloat16 h = __float2bfloat16(v);
        g_w2s[0][o][k] = h;
        g_w2s[1][o][k] = __float2bfloat16(v - __bfloat162float(h));
    }
}

// ================= K1: x_in = w_in @ x via mma.sync (A-hi fragments hoisted) =================
// block: pos=128, o=384 via 6 chunks of 64, K=64 -> 8 A-ktiles (4 hi + 4 lo)
// smem: A 32KB | B 16KB | stg 33KB = 83KB -> 2 blocks/SM
__global__ void __launch_bounds__(256, 2) gemm1_tc(const float* __restrict__ x) {
    extern __shared__ char smem[];
    char* As = smem;                               // 8 * 4096 = 32768
    char* Bs = smem + 32768;                       // 8 * 2048 = 16384
    float* stg = (float*)(smem + 49152);           // 33792 B
    const uint32_t As_u = smem_u32(As), Bs_u = smem_u32(Bs);
    const int t = threadIdx.x, lane = t & 31, w = t >> 5;
    const int g = lane >> 2, q = lane & 3;
    const int b = blockIdx.y, pos0 = blockIdx.x * 128;
    const int wy = w & 3, wx = w >> 2;             // 4 pos-warps x 2 o-warps

    uint32_t a_off[2];
#pragma unroll
    for (int mt = 0; mt < 2; mt++)
        a_off[mt] = row_addr(wy * 32 + mt * 16 + (lane & 15), (lane & 16) ? 16 : 0);
    uint32_t b_off[2];
#pragma unroll
    for (int np = 0; np < 2; np++)
        b_off[np] = row_addr(wx * 32 + np * 16 + ((lane >> 4) & 1) * 8 + (lane & 7),
                             (lane & 8) ? 16 : 0);

    // stage x tile [64c][128pos] f32
    const float* xb = x + ((size_t)b * 64) * HW + pos0;
#pragma unroll
    for (int i = 0; i < 8; i++) {
        int idx = t + i * 256, cc = idx >> 5, p4 = idx & 31;
        *(float4*)&stg[cc * 128 + p4 * 4] = *(const float4*)(xb + (size_t)cc * HW + p4 * 4);
    }
    __syncthreads();
    // convert A -> bf16 hi (ktiles 0..3) / lo (4..7)
#pragma unroll
    for (int i = 0; i < 8; i++) {
        int idx = t + i * 256;
        int pos = idx & 127, k = (idx >> 7) * 4;
        float v0 = stg[(k + 0) * 128 + pos], v1 = stg[(k + 1) * 128 + pos];
        float v2 = stg[(k + 2) * 128 + pos], v3 = stg[(k + 3) * 128 + pos];
        uint2 hi, lo; split4(v0, v1, v2, v3, hi, lo);
        uint32_t ah = tile_addr(k >> 4, pos, (k & 15) * 2, 4096);
        *(uint2*)(As + ah) = hi;
        *(uint2*)(As + ah + 4 * 4096) = lo;
    }
    __syncthreads();

    // hoist A-hi fragments (reused by 8 of 12 k-steps in every chunk)
    uint32_t ahi[4][2][4];
#pragma unroll
    for (int at = 0; at < 4; at++) {
        ldsm4(ahi[at][0], As_u + at * 4096 + a_off[0]);
        ldsm4(ahi[at][1], As_u + at * 4096 + a_off[1]);
    }

    for (int oc = 0; oc < 6; oc++) {
        if (oc) __syncthreads();   // protect B + stg from previous chunk readers
        // fill B chunk: 64 o x (4 hi + 4 lo) ktiles, kstride 2048
#pragma unroll
        for (int i = 0; i < 8; i++) {
            int idx = t + i * 256;
            int pl = idx >> 10;                    // 0..1
            int r  = idx & 1023;
            int o = r >> 4, k = (r & 15) * 4;
            uint2 v = *(const uint2*)&g_w1s[pl][oc * 64 + o][k];
            *(uint2*)(Bs + tile_addr(pl * 4 + (k >> 4), o, (k & 15) * 2, 2048)) = v;
        }
        __syncthreads();

        float acc[2][4][4];
#pragma unroll
        for (int m = 0; m < 2; m++)
#pragma unroll
            for (int n = 0; n < 4; n++)
#pragma unroll
                for (int j = 0; j < 4; j++) acc[m][n][j] = 0.f;

#pragma unroll
        for (int s = 0; s < 12; s++) {
            int bt = (s < 4) ? s : s - 4;    // B: hi,hi,lo
            uint32_t alo[2][4], bf[2][4];
            const uint32_t (*af)[4];
            if (s >= 4 && s < 8) {           // A-lo ktiles 4..7, loaded per chunk
                ldsm4(alo[0], As_u + s * 4096 + a_off[0]);
                ldsm4(alo[1], As_u + s * 4096 + a_off[1]);
                af = alo;
            } else {
                af = ahi[(s < 4) ? s : s - 8];
            }
            ldsm4(bf[0], Bs_u + bt * 2048 + b_off[0]);   // nt 0,1
            ldsm4(bf[1], Bs_u + bt * 2048 + b_off[1]);   // nt 2,3
#pragma unroll
            for (int np = 0; np < 2; np++)
#pragma unroll
                for (int h = 0; h < 2; h++) {            // nt = np*2 + h
                    mma16816(acc[0][np * 2 + h], af[0], &bf[np][h * 2]);
                    mma16816(acc[1][np * 2 + h], af[1], &bf[np][h * 2]);
                }
        }

        // stage acc -> smem [o][pos] with 132-float padded rows
        __syncthreads();
#pragma unroll
        for (int mt = 0; mt < 2; mt++)
#pragma unroll
            for (int nt = 0; nt < 4; nt++) {
                int ol = wx * 32 + nt * 8 + q * 2;
                int pl = wy * 32 + mt * 16 + g;
                stg[ol * 132 + pl]           = acc[mt][nt][0];
                stg[(ol + 1) * 132 + pl]     = acc[mt][nt][1];
                stg[ol * 132 + pl + 8]       = acc[mt][nt][2];
                stg[(ol + 1) * 132 + pl + 8] = acc[mt][nt][3];
            }
        __syncthreads();
        // coalesced store: 64 o-rows x 128 pos
#pragma unroll
        for (int i = 0; i < 8; i++) {
            int idx = t + i * 256, o = idx >> 5, p4 = idx & 31;
            int og = oc * 64 + o;
            if (og < C2) {
                float4 v = *(float4*)&stg[o * 132 + p4 * 4];
                *(float4*)&g_xin[((size_t)(b * C2 + og)) * HW + pos0 + p4 * 4] = v;
            }
        }
    }
}

// ================= K5: out = w_out @ spatial via mma.sync (ldmatrix fragments) =================
__global__ void __launch_bounds__(256, 2) gemm2_tc(float* __restrict__ out) {
    extern __shared__ char smem[];
    char* Bs = smem;                       // 22 * 2048 = 45056
    char* As = smem + 45056;               // 8 * 4096  = 32768
    float* stg = (float*)(smem + 45056 + 32768);
    const uint32_t As_u = smem_u32(As), Bs_u = smem_u32(Bs);
    const int t = threadIdx.x, lane = t & 31, w = t >> 5;
    const int g = lane >> 2, q = lane & 3;
    const int b = blockIdx.y, pos0 = blockIdx.x * 128;
    const int wy = w & 3, wx = w >> 2;

    uint32_t a_off[2];
#pragma unroll
    for (int mt = 0; mt < 2; mt++)
        a_off[mt] = row_addr(wy * 32 + mt * 16 + (lane & 15), (lane & 16) ? 16 : 0);
    uint32_t b_off[2];
#pragma unroll
    for (int np = 0; np < 2; np++)
        b_off[np] = row_addr(wx * 32 + np * 16 + ((lane >> 4) & 1) * 8 + (lane & 7),
                             (lane & 8) ? 16 : 0);

    for (int i = t; i < 2 * 64 * 44; i += 256) {
        int pl = i / (64 * 44), r = i - pl * (64 * 44);
        int o = r / 44, k = (r - o * 44) * 4;
        uint2 v = *(const uint2*)&g_w2s[pl][o][k];
        *(uint2*)(Bs + tile_addr(pl * 11 + (k >> 4), o, (k & 15) * 2, 2048)) = v;
    }

    float acc[2][4][4];
#pragma unroll
    for (int m = 0; m < 2; m++)
#pragma unroll
        for (int n = 0; n < 4; n++)
#pragma unroll
            for (int j = 0; j < 4; j++) acc[m][n][j] = 0.f;

    for (int chunk = 0; chunk < 3; chunk++) {
        const int c0 = chunk * 64;
        const int nk = (chunk == 2) ? 3 : 4;
        __syncthreads();
#pragma unroll
        for (int i = 0; i < 8; i++) {
            int idx = t + i * 256, cc = idx >> 5, p4 = idx & 31;
            int c = c0 + cc;
            float4 v = make_float4(0.f, 0.f, 0.f, 0.f);
            if (c < HIDDEN)
                v = *(const float4*)&g_feat[((size_t)(b * HIDDEN + c)) * HW + pos0 + p4 * 4];
            *(float4*)&stg[cc * 128 + p4 * 4] = v;
        }
        __syncthreads();
#pragma unroll
        for (int i = 0; i < 8; i++) {
            int idx = t + i * 256;
            int pos = idx & 127, kk = (idx >> 7) * 4;
            float v0 = stg[(kk + 0) * 128 + pos], v1 = stg[(kk + 1) * 128 + pos];
            float v2 = stg[(kk + 2) * 128 + pos], v3 = stg[(kk + 3) * 128 + pos];
            uint2 hi, lo; split4(v0, v1, v2, v3, hi, lo);
            uint32_t ah = tile_addr(kk >> 4, pos, (kk & 15) * 2, 4096);
            *(uint2*)(As + ah) = hi;
            *(uint2*)(As + ah + 4 * 4096) = lo;
        }
        __syncthreads();

#pragma unroll
        for (int j = 0; j < 4; j++) {
            if (j >= nk) break;
            uint32_t ah2[2][4], al2[2][4], bh[2][4], bl[2][4];
            ldsm4(ah2[0], As_u + j * 4096 + a_off[0]);
            ldsm4(ah2[1], As_u + j * 4096 + a_off[1]);
            ldsm4(al2[0], As_u + (4 + j) * 4096 + a_off[0]);
            ldsm4(al2[1], As_u + (4 + j) * 4096 + a_off[1]);
            ldsm4(bh[0], Bs_u + (4 * chunk + j) * 2048 + b_off[0]);
            ldsm4(bh[1], Bs_u + (4 * chunk + j) * 2048 + b_off[1]);
            ldsm4(bl[0], Bs_u + (11 + 4 * chunk + j) * 2048 + b_off[0]);
            ldsm4(bl[1], Bs_u + (11 + 4 * chunk + j) * 2048 + b_off[1]);
#pragma unroll
            for (int np = 0; np < 2; np++)
#pragma unroll
                for (int h = 0; h < 2; h++) {
                    int nt = np * 2 + h;
                    mma16816(acc[0][nt], ah2[0], &bh[np][h * 2]);
                    mma16816(acc[1][nt], ah2[1], &bh[np][h * 2]);
                    mma16816(acc[0][nt], al2[0], &bh[np][h * 2]);
                    mma16816(acc[1][nt], al2[1], &bh[np][h * 2]);
                    mma16816(acc[0][nt], ah2[0], &bl[np][h * 2]);
                    mma16816(acc[1][nt], ah2[1], &bl[np][h * 2]);
                }
        }
    }

#pragma unroll
    for (int mt = 0; mt < 2; mt++)
#pragma unroll
        for (int nt = 0; nt < 4; nt++) {
            int o = wx * 32 + nt * 8 + q * 2;
            int pos = pos0 + wy * 32 + mt * 16 + g;
            float* p = out + ((size_t)(b * 64 + o)) * HW + pos;
            p[0]      = acc[mt][nt][0];
            p[HW]     = acc[mt][nt][1];
            p[8]      = acc[mt][nt][2];
            p[HW + 8] = acc[mt][nt][3];
        }
}

// ================= K2: depthwise 3x3 + gelu gate + gap partials =================
__device__ __forceinline__ float gelu_exact(float x) {
    return 0.5f * x * (1.f + erff(x * 0.70710678118654752f));
}

__global__ void __launch_bounds__(256) dwk(const float* __restrict__ w_dw) {
    const int bc = blockIdx.z;
    const int b = bc / HIDDEN, c = bc % HIDDEN;
    const int t = threadIdx.x;
    const int tx = t & 15, ty = t >> 4;
    const int w0 = blockIdx.x * 128 + tx * 8;
    const int h0 = blockIdx.y * 32 + ty * 2;      // output rows h0, h0+1

    float acc[2][2][8];                           // [ch][outrow][col]
#pragma unroll
    for (int ch = 0; ch < 2; ch++)
#pragma unroll
        for (int orr = 0; orr < 2; orr++)
#pragma unroll
            for (int j = 0; j < 8; j++) acc[ch][orr][j] = 0.f;

#pragma unroll
    for (int ch = 0; ch < 2; ch++) {
        const float* bp = g_xin + ((size_t)(b * C2 + c + ch * HIDDEN)) * HW;
        const float* wt = w_dw + (c + ch * HIDDEN) * 9;
        float k[9];
#pragma unroll
        for (int j = 0; j < 9; j++) k[j] = __ldg(wt + j);

#pragma unroll
        for (int r = 0; r < 4; r++) {             // input rows h0-1 .. h0+2
            int gh = h0 - 1 + r;
            bool ok = (gh >= 0) && (gh <= 255);
            const float* row = bp + gh * WIDTH + w0;
            float4 m0 = make_float4(0.f, 0.f, 0.f, 0.f);
            float4 m1 = make_float4(0.f, 0.f, 0.f, 0.f);
            if (ok) { m0 = *(const float4*)row; m1 = *(const float4*)(row + 4); }
            float lft = __shfl_up_sync(0xffffffffu, m1.w, 1);
            float rgt = __shfl_down_sync(0xffffffffu, m0.x, 1);
            if (tx == 0)  lft = (ok && w0 > 0)   ? __ldg(row - 1) : 0.f;
            if (tx == 15) rgt = (ok && w0 < 248) ? __ldg(row + 8) : 0.f;
            float v[10] = {lft, m0.x, m0.y, m0.z, m0.w, m1.x, m1.y, m1.z, m1.w, rgt};
            if (r < 3) {
                float c0 = k[r * 3], c1 = k[r * 3 + 1], c2 = k[r * 3 + 2];
#pragma unroll
                for (int j = 0; j < 8; j++)
                    acc[ch][0][j] += c0 * v[j] + c1 * v[j + 1] + c2 * v[j + 2];
            }
            if (r >= 1) {
                float c0 = k[(r - 1) * 3], c1 = k[(r - 1) * 3 + 1], c2 = k[(r - 1) * 3 + 2];
#pragma unroll
                for (int j = 0; j < 8; j++)
                    acc[ch][1][j] += c0 * v[j] + c1 * v[j + 1] + c2 * v[j + 2];
            }
        }
    }

    float s = 0.f;
#pragma unroll
    for (int orr = 0; orr < 2; orr++) {
        float f[8];
#pragma unroll
        for (int j = 0; j < 8; j++) {
            f[j] = gelu_exact(acc[0][orr][j]) * acc[1][orr][j];
            s += f[j];
        }
        float* op = g_feat + ((size_t)bc) * HW + (h0 + orr) * WIDTH + w0;
        *(float4*)op       = make_float4(f[0], f[1], f[2], f[3]);
        *(float4*)(op + 4) = make_float4(f[4], f[5], f[6], f[7]);
    }

    __shared__ float red[256];
    red[t] = s;
    __syncthreads();
#pragma unroll
    for (int off = 128; off > 0; off >>= 1) {
        if (t < off) red[t] += red[t + off];
        __syncthreads();
    }
    if (t == 0)
        g_part[bc * PARTS + blockIdx.y * 2 + blockIdx.x] = red[0];
}

// ================= K4: per-patch rfft2 * S -> irfft2 (modulation fused in) =================
__device__ __forceinline__ float2 cmul(float2 a, float2 b) {
    return make_float2(a.x * b.x - a.y * b.y, a.x * b.y + a.y * b.x);
}
__device__ __forceinline__ float2 cadd(float2 a, float2 b) { return make_float2(a.x + b.x, a.y + b.y); }
__device__ __forceinline__ float2 csub(float2 a, float2 b) { return make_float2(a.x - b.x, a.y - b.y); }

template <int SIGN>
__device__ __forceinline__ void cfft8(float2 x[8]) {
    float2 e0 = x[0], e1 = x[2], e2 = x[4], e3 = x[6];
    float2 o0 = x[1], o1 = x[3], o2 = x[5], o3 = x[7];
    float2 t0 = cadd(e0, e2), t1 = csub(e0, e2), t2 = cadd(e1, e3), t3 = csub(e1, e3);
    float2 rt3 = (SIGN < 0) ? make_float2(t3.y, -t3.x) : make_float2(-t3.y, t3.x);
    float2 E0 = cadd(t0, t2), E2 = csub(t0, t2), E1 = cadd(t1, rt3), E3 = csub(t1, rt3);
    t0 = cadd(o0, o2); t1 = csub(o0, o2); t2 = cadd(o1, o3); t3 = csub(o1, o3);
    rt3 = (SIGN < 0) ? make_float2(t3.y, -t3.x) : make_float2(-t3.y, t3.x);
    float2 O0 = cadd(t0, t2), O2 = csub(t0, t2), O1 = cadd(t1, rt3), O3 = csub(t1, rt3);
    const float s = 0.70710678118654752f;
    const float2 w1 = make_float2(s, (SIGN < 0) ? -s : s);
    const float2 w2 = make_float2(0.f, (SIGN < 0) ? -1.f : 1.f);
    const float2 w3 = make_float2(-s, (SIGN < 0) ? -s : s);
    float2 a;
    a = O0;           x[0] = cadd(E0, a); x[4] = csub(E0, a);
    a = cmul(w1, O1); x[1] = cadd(E1, a); x[5] = csub(E1, a);
    a = cmul(w2, O2); x[2] = cadd(E2, a); x[6] = csub(E2, a);
    a = cmul(w3, O3); x[3] = cadd(E3, a); x[7] = csub(E3, a);
}

__device__ __forceinline__ void rfft8(float4 r0, float4 r1, float2 out[5]) {
    float e0 = r0.x, e1 = r0.z, e2 = r1.x, e3 = r1.z;
    float o0 = r0.y, o1 = r0.w, o2 = r1.y, o3 = r1.w;
    float ep = e0 + e2, em = e0 - e2, eq = e1 + e3, er = e1 - e3;
    float op = o0 + o2, om = o0 - o2, oq = o1 + o3, orr = o1 - o3;
    float E0 = ep + eq, E2 = ep - eq;
    float O0 = op + oq, O2 = op - oq;
    const float s = 0.70710678118654752f;
    float w1x = s * (om - orr), w1y = s * (-orr - om);
    float w3x = s * (orr - om), w3y = -s * (om + orr);
    out[0] = make_float2(E0 + O0, 0.f);
    out[1] = make_float2(em + w1x, -er + w1y);
    out[2] = make_float2(E2, -O2);
    out[3] = make_float2(em + w3x, er + w3y);
    out[4] = make_float2(E0 - O0, 0.f);
}

__global__ void __launch_bounds__(256) fftk(const float* __restrict__ Wr,
                                            const float* __restrict__ Wi,
                                            const float* __restrict__ csc,
                                            const float* __restrict__ w_mod1,
                                            const float* __restrict__ w_mod2) {
    const int bc = blockIdx.y;
    const int b = bc / HIDDEN, c = bc % HIDDEN;
    __shared__ float gap_s[HIDDEN];
    __shared__ float relu_s[16];
    __shared__ float mod_sh[1];
    __shared__ float2 S[PP * PF];
    const int t = threadIdx.x;

    // --- fused modulation scalar (per batch b, recomputed per block; g_part L2-resident) ---
    for (int cc = t; cc < HIDDEN; cc += 256) {
        const float* p = g_part + (size_t)(b * HIDDEN + cc) * PARTS;
        float s = 0.f;
#pragma unroll
        for (int j = 0; j < PARTS; j++) s += p[j];
        gap_s[cc] = s * (1.f / 65536.f);
    }
    __syncthreads();
    const int wid = t >> 5, lane = t & 31;
    for (int j = wid; j < 10; j += 8) {
        float s = 0.f;
        for (int cc = lane; cc < HIDDEN; cc += 32)
            s += gap_s[cc] * w_mod1[j * HIDDEN + cc];
#pragma unroll
        for (int off = 16; off > 0; off >>= 1) s += __shfl_xor_sync(0xffffffff, s, off);
        if (lane == 0) relu_s[j] = fmaxf(s, 0.f);
    }
    __syncthreads();
    if (t == 0) {
        float m = 0.f;
#pragma unroll
        for (int j = 0; j < 10; j++) m += relu_s[j] * w_mod2[j];
        mod_sh[0] = 1.f / (1.f + expf(-m));
    }
    __syncthreads();

    if (t < PP * PF) {
        int ky = t / PF, kx = t % PF;
        float mask = expf(-(float)(ky * ky + kx * kx) * (1.f / 18.f));
        float boost = 1.f + mask * (csc[c] * (0.5f + mod_sh[0]));
        float sc = boost * (1.f / 64.f);
        S[t] = make_float2(Wr[c * 40 + t] * sc, Wi[c * 40 + t] * sc);
    }
    __syncthreads();

    const int p = blockIdx.x * 256 + t;
    float* base = g_feat + (((size_t)bc) << 16) + (p >> 5) * (PP * WIDTH) + (p & 31) * PP;

    float2 F[5][8];
#pragma unroll
    for (int y = 0; y < 8; y++) {
        float4 r0 = *(const float4*)(base + y * WIDTH);
        float4 r1 = *(const float4*)(base + y * WIDTH + 4);
        float2 o5[5];
        rfft8(r0, r1, o5);
#pragma unroll
        for (int k = 0; k < 5; k++) F[k][y] = o5[k];
    }
#pragma unroll
    for (int k = 0; k < 5; k++) cfft8<-1>(F[k]);
#pragma unroll
    for (int k = 0; k < 5; k++)
#pragma unroll
        for (int ky = 0; ky < 8; ky++)
            F[k][ky] = cmul(F[k][ky], S[ky * PF + k]);
#pragma unroll
    for (int k = 0; k < 5; k++) cfft8<1>(F[k]);
#pragma unroll
    for (int y = 0; y < 8; y++) {
        float2 z[8];
        z[0] = make_float2(F[0][y].x, 0.f);
        z[1] = F[1][y]; z[2] = F[2][y]; z[3] = F[3][y];
        z[4] = make_float2(F[4][y].x, 0.f);
        z[5] = make_float2(F[3][y].x, -F[3][y].y);
        z[6] = make_float2(F[2][y].x, -F[2][y].y);
        z[7] = make_float2(F[1][y].x, -F[1][y].y);
        cfft8<1>(z);
        *(float4*)(base + y * WIDTH)     = make_float4(z[0].x, z[1].x, z[2].x, z[3].x);
        *(float4*)(base + y * WIDTH + 4) = make_float4(z[4].x, z[5].x, z[6].x, z[7].x);
    }
}

// ================= launch =================
extern "C" void kernel_launch(void* const* d_in, const int* in_sizes, int n_in,
                              void* d_out, int out_size) {
    const float* x     = (const float*)d_in[0];
    const float* w_in  = (const float*)d_in[1];
    const float* w_dw  = (const float*)d_in[2];
    const float* w_out = (const float*)d_in[3];
    const float* Wr    = (const float*)d_in[4];
    const float* Wi    = (const float*)d_in[5];
    const float* csc   = (const float*)d_in[6];
    const float* wm1   = (const float*)d_in[7];
    const float* wm2   = (const float*)d_in[8];
    float* out = (float*)d_out;

    cudaFuncSetAttribute(gemm1_tc, cudaFuncAttributeMaxDynamicSharedMemorySize, 82944);
    cudaFuncSetAttribute(gemm2_tc, cudaFuncAttributeMaxDynamicSharedMemorySize, 110592);

    wsplit<<<96, 256>>>(w_in, w_out);
    gemm1_tc<<<dim3(512, BATCH), 256, 82944>>>(x);
    dwk<<<dim3(2, 8, BATCH * HIDDEN), 256>>>(w_dw);
    fftk<<<dim3(4, BATCH * HIDDEN), 256>>>(Wr, Wi, csc, wm1, wm2);   // launch index 3 -> ncu window
    gemm2_tc<<<dim3(512, BATCH), 256, 110592>>>(out);
}

// round 13
// speedup vs baseline: 1.0476x; 1.0476x over previous
#include <cuda_runtime.h>
#include <cuda_bf16.h>
#include <math.h>
#include <cstdint>

// ---------------- constants ----------------
#define BATCH   4
#define DIM     64
#define HIDDEN  170
#define C2      340           // 2*HIDDEN
#define HW      65536         // 256*256
#define WIDTH   256
#define PP      8
#define PF      5
#define PARTS   16            // gap partials per (b,c)

// ---------------- scratch (device globals; no allocation allowed) ----------------
__device__ float g_xin [(size_t)BATCH * C2 * HW];      // 356 MB
__device__ float g_feat[(size_t)BATCH * HIDDEN * HW];  // 178 MB (feat, then spatial in-place)
__device__ float g_part[BATCH * HIDDEN * PARTS];
__device__ float g_mod [BATCH];
__device__ __nv_bfloat16 g_w1s[2][384][64];            // w_in  split: [hi/lo][o pad][k]
__device__ __nv_bfloat16 g_w2s[2][64][176];            // w_out split: [hi/lo][o][k pad]

// ---------------- helpers ----------------
__device__ __forceinline__ uint32_t smem_u32(const void* p) {
    uint32_t a;
    asm("{ .reg .u64 t; cvta.to.shared.u64 t, %1; cvt.u32.u64 %0, t; }" : "=r"(a) : "l"(p));
    return a;
}
__device__ __forceinline__ uint32_t pack2(float a, float b) {
    uint32_t r;
    asm("cvt.rn.bf16x2.f32 %0, %1, %2;" : "=r"(r) : "f"(b), "f"(a));
    return r;
}
__device__ __forceinline__ void split4(float v0, float v1, float v2, float v3,
                                       uint2& hi, uint2& lo) {
    uint32_t h01 = pack2(v0, v1), h23 = pack2(v2, v3);
    float f0 = __uint_as_float(h01 << 16),  f1 = __uint_as_float(h01 & 0xffff0000u);
    float f2 = __uint_as_float(h23 << 16),  f3 = __uint_as_float(h23 & 0xffff0000u);
    hi = make_uint2(h01, h23);
    lo = make_uint2(pack2(v0 - f0, v1 - f1), pack2(v2 - f2, v3 - f3));
}

__device__ __forceinline__ void mma16816(float d[4], const uint32_t a[4], const uint32_t b[2]) {
    asm volatile(
        "mma.sync.aligned.m16n8k16.row.col.f32.bf16.bf16.f32 "
        "{%0,%1,%2,%3}, {%4,%5,%6,%7}, {%8,%9}, {%0,%1,%2,%3};"
        : "+f"(d[0]), "+f"(d[1]), "+f"(d[2]), "+f"(d[3])
        : "r"(a[0]), "r"(a[1]), "r"(a[2]), "r"(a[3]), "r"(b[0]), "r"(b[1]));
}
__device__ __forceinline__ void ldsm4(uint32_t* r, uint32_t addr) {
    asm volatile("ldmatrix.sync.aligned.m8n8.x4.shared.b16 {%0,%1,%2,%3}, [%4];"
        : "=r"(r[0]), "=r"(r[1]), "=r"(r[2]), "=r"(r[3]) : "r"(addr));
}

// smem tile layout: [ktile][row][16 bf16 = 32B], bit-4 XOR swizzle on (row>>2)&1
__device__ __forceinline__ uint32_t tile_addr(int ktile, int row, int kin2bytes, int kstride) {
    return (uint32_t)(ktile * kstride + ((row * 32 + kin2bytes) ^ (((row >> 2) & 1) << 4)));
}
__device__ __forceinline__ uint32_t row_addr(int row, int byte16) {
    return (uint32_t)((row * 32 + byte16) ^ (((row >> 2) & 1) << 4));
}

// ================= K0: weight split prep =================
__global__ void __launch_bounds__(256) wsplit(const float* __restrict__ w_in,
                                              const float* __restrict__ w_out) {
    int i = blockIdx.x * 256 + threadIdx.x;
    if (i < 384 * 64) {
        int o = i >> 6, k = i & 63;
        float v = (o < C2) ? w_in[o * 64 + k] : 0.f;
        __nv_bfloat16 h = __float2bfloat16(v);
        g_w1s[0][o][k] = h;
        g_w1s[1][o][k] = __float2bfloat16(v - __bfloat162float(h));
    }
    if (i < 64 * 176) {
        int o = i / 176, k = i - o * 176;
        float v = (k < HIDDEN) ? w_out[o * HIDDEN + k] : 0.f;
        __nv_bfloat16 h = __float2bfloat16(v);
        g_w2s[0][o][k] = h;
        g_w2s[1][o][k] = __float2bfloat16(v - __bfloat162float(h));
    }
}

__global__ void noop() {}

// ================= K1: x_in = w_in @ x via mma.sync (A-hi fragments hoisted) =================
__global__ void __launch_bounds__(256, 2) gemm1_tc(const float* __restrict__ x) {
    extern __shared__ char smem[];
    char* As = smem;                               // 8 * 4096 = 32768
    char* Bs = smem + 32768;                       // 8 * 2048 = 16384
    float* stg = (float*)(smem + 49152);           // 33792 B
    const uint32_t As_u = smem_u32(As), Bs_u = smem_u32(Bs);
    const int t = threadIdx.x, lane = t & 31, w = t >> 5;
    const int g = lane >> 2, q = lane & 3;
    const int b = blockIdx.y, pos0 = blockIdx.x * 128;
    const int wy = w & 3, wx = w >> 2;             // 4 pos-warps x 2 o-warps

    uint32_t a_off[2];
#pragma unroll
    for (int mt = 0; mt < 2; mt++)
        a_off[mt] = row_addr(wy * 32 + mt * 16 + (lane & 15), (lane & 16) ? 16 : 0);
    uint32_t b_off[2];
#pragma unroll
    for (int np = 0; np < 2; np++)
        b_off[np] = row_addr(wx * 32 + np * 16 + ((lane >> 4) & 1) * 8 + (lane & 7),
                             (lane & 8) ? 16 : 0);

    const float* xb = x + ((size_t)b * 64) * HW + pos0;
#pragma unroll
    for (int i = 0; i < 8; i++) {
        int idx = t + i * 256, cc = idx >> 5, p4 = idx & 31;
        *(float4*)&stg[cc * 128 + p4 * 4] = *(const float4*)(xb + (size_t)cc * HW + p4 * 4);
    }
    __syncthreads();
#pragma unroll
    for (int i = 0; i < 8; i++) {
        int idx = t + i * 256;
        int pos = idx & 127, k = (idx >> 7) * 4;
        float v0 = stg[(k + 0) * 128 + pos], v1 = stg[(k + 1) * 128 + pos];
        float v2 = stg[(k + 2) * 128 + pos], v3 = stg[(k + 3) * 128 + pos];
        uint2 hi, lo; split4(v0, v1, v2, v3, hi, lo);
        uint32_t ah = tile_addr(k >> 4, pos, (k & 15) * 2, 4096);
        *(uint2*)(As + ah) = hi;
        *(uint2*)(As + ah + 4 * 4096) = lo;
    }
    __syncthreads();

    uint32_t ahi[4][2][4];
#pragma unroll
    for (int at = 0; at < 4; at++) {
        ldsm4(ahi[at][0], As_u + at * 4096 + a_off[0]);
        ldsm4(ahi[at][1], As_u + at * 4096 + a_off[1]);
    }

    for (int oc = 0; oc < 6; oc++) {
        if (oc) __syncthreads();
#pragma unroll
        for (int i = 0; i < 8; i++) {
            int idx = t + i * 256;
            int pl = idx >> 10;
            int r  = idx & 1023;
            int o = r >> 4, k = (r & 15) * 4;
            uint2 v = *(const uint2*)&g_w1s[pl][oc * 64 + o][k];
            *(uint2*)(Bs + tile_addr(pl * 4 + (k >> 4), o, (k & 15) * 2, 2048)) = v;
        }
        __syncthreads();

        float acc[2][4][4];
#pragma unroll
        for (int m = 0; m < 2; m++)
#pragma unroll
            for (int n = 0; n < 4; n++)
#pragma unroll
                for (int j = 0; j < 4; j++) acc[m][n][j] = 0.f;

#pragma unroll
        for (int s = 0; s < 12; s++) {
            int bt = (s < 4) ? s : s - 4;    // B: hi,hi,lo
            uint32_t alo[2][4], bf[2][4];
            const uint32_t (*af)[4];
            if (s >= 4 && s < 8) {
                ldsm4(alo[0], As_u + s * 4096 + a_off[0]);
                ldsm4(alo[1], As_u + s * 4096 + a_off[1]);
                af = alo;
            } else {
                af = ahi[(s < 4) ? s : s - 8];
            }
            ldsm4(bf[0], Bs_u + bt * 2048 + b_off[0]);
            ldsm4(bf[1], Bs_u + bt * 2048 + b_off[1]);
#pragma unroll
            for (int np = 0; np < 2; np++)
#pragma unroll
                for (int h = 0; h < 2; h++) {
                    mma16816(acc[0][np * 2 + h], af[0], &bf[np][h * 2]);
                    mma16816(acc[1][np * 2 + h], af[1], &bf[np][h * 2]);
                }
        }

        __syncthreads();
#pragma unroll
        for (int mt = 0; mt < 2; mt++)
#pragma unroll
            for (int nt = 0; nt < 4; nt++) {
                int ol = wx * 32 + nt * 8 + q * 2;
                int pl = wy * 32 + mt * 16 + g;
                stg[ol * 132 + pl]           = acc[mt][nt][0];
                stg[(ol + 1) * 132 + pl]     = acc[mt][nt][1];
                stg[ol * 132 + pl + 8]       = acc[mt][nt][2];
                stg[(ol + 1) * 132 + pl + 8] = acc[mt][nt][3];
            }
        __syncthreads();
#pragma unroll
        for (int i = 0; i < 8; i++) {
            int idx = t + i * 256, o = idx >> 5, p4 = idx & 31;
            int og = oc * 64 + o;
            if (og < C2) {
                float4 v = *(float4*)&stg[o * 132 + p4 * 4];
                *(float4*)&g_xin[((size_t)(b * C2 + og)) * HW + pos0 + p4 * 4] = v;
            }
        }
    }
}

// ================= K5: out = w_out @ spatial via mma.sync (ldmatrix fragments) =================
__global__ void __launch_bounds__(256, 2) gemm2_tc(float* __restrict__ out) {
    extern __shared__ char smem[];
    char* Bs = smem;                       // 22 * 2048 = 45056
    char* As = smem + 45056;               // 8 * 4096  = 32768
    float* stg = (float*)(smem + 45056 + 32768);
    const uint32_t As_u = smem_u32(As), Bs_u = smem_u32(Bs);
    const int t = threadIdx.x, lane = t & 31, w = t >> 5;
    const int g = lane >> 2, q = lane & 3;
    const int b = blockIdx.y, pos0 = blockIdx.x * 128;
    const int wy = w & 3, wx = w >> 2;

    uint32_t a_off[2];
#pragma unroll
    for (int mt = 0; mt < 2; mt++)
        a_off[mt] = row_addr(wy * 32 + mt * 16 + (lane & 15), (lane & 16) ? 16 : 0);
    uint32_t b_off[2];
#pragma unroll
    for (int np = 0; np < 2; np++)
        b_off[np] = row_addr(wx * 32 + np * 16 + ((lane >> 4) & 1) * 8 + (lane & 7),
                             (lane & 8) ? 16 : 0);

    for (int i = t; i < 2 * 64 * 44; i += 256) {
        int pl = i / (64 * 44), r = i - pl * (64 * 44);
        int o = r / 44, k = (r - o * 44) * 4;
        uint2 v = *(const uint2*)&g_w2s[pl][o][k];
        *(uint2*)(Bs + tile_addr(pl * 11 + (k >> 4), o, (k & 15) * 2, 2048)) = v;
    }

    float acc[2][4][4];
#pragma unroll
    for (int m = 0; m < 2; m++)
#pragma unroll
        for (int n = 0; n < 4; n++)
#pragma unroll
            for (int j = 0; j < 4; j++) acc[m][n][j] = 0.f;

    for (int chunk = 0; chunk < 3; chunk++) {
        const int c0 = chunk * 64;
        const int nk = (chunk == 2) ? 3 : 4;
        __syncthreads();
#pragma unroll
        for (int i = 0; i < 8; i++) {
            int idx = t + i * 256, cc = idx >> 5, p4 = idx & 31;
            int c = c0 + cc;
            float4 v = make_float4(0.f, 0.f, 0.f, 0.f);
            if (c < HIDDEN)
                v = *(const float4*)&g_feat[((size_t)(b * HIDDEN + c)) * HW + pos0 + p4 * 4];
            *(float4*)&stg[cc * 128 + p4 * 4] = v;
        }
        __syncthreads();
#pragma unroll
        for (int i = 0; i < 8; i++) {
            int idx = t + i * 256;
            int pos = idx & 127, kk = (idx >> 7) * 4;
            float v0 = stg[(kk + 0) * 128 + pos], v1 = stg[(kk + 1) * 128 + pos];
            float v2 = stg[(kk + 2) * 128 + pos], v3 = stg[(kk + 3) * 128 + pos];
            uint2 hi, lo; split4(v0, v1, v2, v3, hi, lo);
            uint32_t ah = tile_addr(kk >> 4, pos, (kk & 15) * 2, 4096);
            *(uint2*)(As + ah) = hi;
            *(uint2*)(As + ah + 4 * 4096) = lo;
        }
        __syncthreads();

#pragma unroll
        for (int j = 0; j < 4; j++) {
            if (j >= nk) break;
            uint32_t ah2[2][4], al2[2][4], bh[2][4], bl[2][4];
            ldsm4(ah2[0], As_u + j * 4096 + a_off[0]);
            ldsm4(ah2[1], As_u + j * 4096 + a_off[1]);
            ldsm4(al2[0], As_u + (4 + j) * 4096 + a_off[0]);
            ldsm4(al2[1], As_u + (4 + j) * 4096 + a_off[1]);
            ldsm4(bh[0], Bs_u + (4 * chunk + j) * 2048 + b_off[0]);
            ldsm4(bh[1], Bs_u + (4 * chunk + j) * 2048 + b_off[1]);
            ldsm4(bl[0], Bs_u + (11 + 4 * chunk + j) * 2048 + b_off[0]);
            ldsm4(bl[1], Bs_u + (11 + 4 * chunk + j) * 2048 + b_off[1]);
#pragma unroll
            for (int np = 0; np < 2; np++)
#pragma unroll
                for (int h = 0; h < 2; h++) {
                    int nt = np * 2 + h;
                    mma16816(acc[0][nt], ah2[0], &bh[np][h * 2]);
                    mma16816(acc[1][nt], ah2[1], &bh[np][h * 2]);
                    mma16816(acc[0][nt], al2[0], &bh[np][h * 2]);
                    mma16816(acc[1][nt], al2[1], &bh[np][h * 2]);
                    mma16816(acc[0][nt], ah2[0], &bl[np][h * 2]);
                    mma16816(acc[1][nt], ah2[1], &bl[np][h * 2]);
                }
        }
    }

#pragma unroll
    for (int mt = 0; mt < 2; mt++)
#pragma unroll
        for (int nt = 0; nt < 4; nt++) {
            int o = wx * 32 + nt * 8 + q * 2;
            int pos = pos0 + wy * 32 + mt * 16 + g;
            float* p = out + ((size_t)(b * 64 + o)) * HW + pos;
            p[0]      = acc[mt][nt][0];
            p[HW]     = acc[mt][nt][1];
            p[8]      = acc[mt][nt][2];
            p[HW + 8] = acc[mt][nt][3];
        }
}

// ================= K2: depthwise 3x3 + gelu gate + gap partials =================
// register-blocked 2 rows x 8 cols per thread, halo via shuffle, y-edge specialization
__device__ __forceinline__ float gelu_exact(float x) {
    return 0.5f * x * (1.f + erff(x * 0.70710678118654752f));
}

template <bool EDGE>
__device__ __forceinline__ void dwk_conv(const float* __restrict__ bp,
                                         const float* __restrict__ wt,
                                         int h0, int w0, int tx, float acc[2][8]) {
    float k[9];
#pragma unroll
    for (int j = 0; j < 9; j++) k[j] = __ldg(wt + j);

#pragma unroll
    for (int r = 0; r < 4; r++) {             // input rows h0-1 .. h0+2
        const int gh = h0 - 1 + r;
        const float* row = bp + gh * WIDTH + w0;
        float4 m0, m1;
        bool ok = true;
        if (EDGE) {
            ok = (gh >= 0) && (gh <= 255);
            m0 = make_float4(0.f, 0.f, 0.f, 0.f);
            m1 = make_float4(0.f, 0.f, 0.f, 0.f);
            if (ok) { m0 = *(const float4*)row; m1 = *(const float4*)(row + 4); }
        } else {
            m0 = *(const float4*)row;
            m1 = *(const float4*)(row + 4);
        }
        float lft = __shfl_up_sync(0xffffffffu, m1.w, 1);
        float rgt = __shfl_down_sync(0xffffffffu, m0.x, 1);
        if (tx == 0)  lft = (ok && w0 > 0)   ? __ldg(row - 1) : 0.f;
        if (tx == 15) rgt = (ok && w0 < 248) ? __ldg(row + 8) : 0.f;
        float v[10] = {lft, m0.x, m0.y, m0.z, m0.w, m1.x, m1.y, m1.z, m1.w, rgt};
        if (r < 3) {
            float c0 = k[r * 3], c1 = k[r * 3 + 1], c2 = k[r * 3 + 2];
#pragma unroll
            for (int j = 0; j < 8; j++)
                acc[0][j] += c0 * v[j] + c1 * v[j + 1] + c2 * v[j + 2];
        }
        if (r >= 1) {
            float c0 = k[(r - 1) * 3], c1 = k[(r - 1) * 3 + 1], c2 = k[(r - 1) * 3 + 2];
#pragma unroll
            for (int j = 0; j < 8; j++)
                acc[1][j] += c0 * v[j] + c1 * v[j + 1] + c2 * v[j + 2];
        }
    }
}

__global__ void __launch_bounds__(256) dwk(const float* __restrict__ w_dw) {
    const int bc = blockIdx.z;
    const int b = bc / HIDDEN, c = bc % HIDDEN;
    const int t = threadIdx.x;
    const int tx = t & 15, ty = t >> 4;
    const int w0 = blockIdx.x * 128 + tx * 8;
    const int h0 = blockIdx.y * 32 + ty * 2;      // output rows h0, h0+1

    float a0[2][8], a1[2][8];
#pragma unroll
    for (int orr = 0; orr < 2; orr++)
#pragma unroll
        for (int j = 0; j < 8; j++) { a0[orr][j] = 0.f; a1[orr][j] = 0.f; }

    const float* bp0 = g_xin + ((size_t)(b * C2 + c)) * HW;
    const float* bp1 = g_xin + ((size_t)(b * C2 + c + HIDDEN)) * HW;
    const float* wt0 = w_dw + c * 9;
    const float* wt1 = w_dw + (c + HIDDEN) * 9;

    if (blockIdx.y == 0 || blockIdx.y == 7) {
        dwk_conv<true>(bp0, wt0, h0, w0, tx, a0);
        dwk_conv<true>(bp1, wt1, h0, w0, tx, a1);
    } else {
        dwk_conv<false>(bp0, wt0, h0, w0, tx, a0);
        dwk_conv<false>(bp1, wt1, h0, w0, tx, a1);
    }

    float s = 0.f;
#pragma unroll
    for (int orr = 0; orr < 2; orr++) {
        float f[8];
#pragma unroll
        for (int j = 0; j < 8; j++) {
            f[j] = gelu_exact(a0[orr][j]) * a1[orr][j];
            s += f[j];
        }
        float* op = g_feat + ((size_t)bc) * HW + (h0 + orr) * WIDTH + w0;
        *(float4*)op       = make_float4(f[0], f[1], f[2], f[3]);
        *(float4*)(op + 4) = make_float4(f[4], f[5], f[6], f[7]);
    }

    __shared__ float red[256];
    red[t] = s;
    __syncthreads();
#pragma unroll
    for (int off = 128; off > 0; off >>= 1) {
        if (t < off) red[t] += red[t + off];
        __syncthreads();
    }
    if (t == 0)
        g_part[bc * PARTS + blockIdx.y * 2 + blockIdx.x] = red[0];
}

// ================= K3: gap reduce + modulation =================
__global__ void __launch_bounds__(256) modk(const float* __restrict__ w_mod1,
                                            const float* __restrict__ w_mod2) {
    const int b = blockIdx.x;
    const int t = threadIdx.x;
    __shared__ float gap_s[HIDDEN];
    __shared__ float relu_s[16];

    for (int c = t; c < HIDDEN; c += 256) {
        const float* p = g_part + (size_t)(b * HIDDEN + c) * PARTS;
        float s = 0.f;
#pragma unroll
        for (int j = 0; j < PARTS; j++) s += p[j];
        gap_s[c] = s * (1.f / 65536.f);
    }
    __syncthreads();

    const int wid = t >> 5, lane = t & 31;
    for (int j = wid; j < 10; j += 8) {
        float s = 0.f;
        for (int c = lane; c < HIDDEN; c += 32)
            s += gap_s[c] * w_mod1[j * HIDDEN + c];
#pragma unroll
        for (int off = 16; off > 0; off >>= 1) s += __shfl_xor_sync(0xffffffff, s, off);
        if (lane == 0) relu_s[j] = fmaxf(s, 0.f);
    }
    __syncthreads();
    if (t == 0) {
        float m = 0.f;
#pragma unroll
        for (int j = 0; j < 10; j++) m += relu_s[j] * w_mod2[j];
        g_mod[b] = 1.f / (1.f + expf(-m));
    }
}

// ================= K4: per-patch rfft2 * S -> irfft2 =================
__device__ __forceinline__ float2 cmul(float2 a, float2 b) {
    return make_float2(a.x * b.x - a.y * b.y, a.x * b.y + a.y * b.x);
}
__device__ __forceinline__ float2 cadd(float2 a, float2 b) { return make_float2(a.x + b.x, a.y + b.y); }
__device__ __forceinline__ float2 csub(float2 a, float2 b) { return make_float2(a.x - b.x, a.y - b.y); }

template <int SIGN>
__device__ __forceinline__ void cfft8(float2 x[8]) {
    float2 e0 = x[0], e1 = x[2], e2 = x[4], e3 = x[6];
    float2 o0 = x[1], o1 = x[3], o2 = x[5], o3 = x[7];
    float2 t0 = cadd(e0, e2), t1 = csub(e0, e2), t2 = cadd(e1, e3), t3 = csub(e1, e3);
    float2 rt3 = (SIGN < 0) ? make_float2(t3.y, -t3.x) : make_float2(-t3.y, t3.x);
    float2 E0 = cadd(t0, t2), E2 = csub(t0, t2), E1 = cadd(t1, rt3), E3 = csub(t1, rt3);
    t0 = cadd(o0, o2); t1 = csub(o0, o2); t2 = cadd(o1, o3); t3 = csub(o1, o3);
    rt3 = (SIGN < 0) ? make_float2(t3.y, -t3.x) : make_float2(-t3.y, t3.x);
    float2 O0 = cadd(t0, t2), O2 = csub(t0, t2), O1 = cadd(t1, rt3), O3 = csub(t1, rt3);
    const float s = 0.70710678118654752f;
    const float2 w1 = make_float2(s, (SIGN < 0) ? -s : s);
    const float2 w2 = make_float2(0.f, (SIGN < 0) ? -1.f : 1.f);
    const float2 w3 = make_float2(-s, (SIGN < 0) ? -s : s);
    float2 a;
    a = O0;           x[0] = cadd(E0, a); x[4] = csub(E0, a);
    a = cmul(w1, O1); x[1] = cadd(E1, a); x[5] = csub(E1, a);
    a = cmul(w2, O2); x[2] = cadd(E2, a); x[6] = csub(E2, a);
    a = cmul(w3, O3); x[3] = cadd(E3, a); x[7] = csub(E3, a);
}

__device__ __forceinline__ void rfft8(float4 r0, float4 r1, float2 out[5]) {
    float e0 = r0.x, e1 = r0.z, e2 = r1.x, e3 = r1.z;
    float o0 = r0.y, o1 = r0.w, o2 = r1.y, o3 = r1.w;
    float ep = e0 + e2, em = e0 - e2, eq = e1 + e3, er = e1 - e3;
    float op = o0 + o2, om = o0 - o2, oq = o1 + o3, orr = o1 - o3;
    float E0 = ep + eq, E2 = ep - eq;
    float O0 = op + oq, O2 = op - oq;
    const float s = 0.70710678118654752f;
    float w1x = s * (om - orr), w1y = s * (-orr - om);
    float w3x = s * (orr - om), w3y = -s * (om + orr);
    out[0] = make_float2(E0 + O0, 0.f);
    out[1] = make_float2(em + w1x, -er + w1y);
    out[2] = make_float2(E2, -O2);
    out[3] = make_float2(em + w3x, er + w3y);
    out[4] = make_float2(E0 - O0, 0.f);
}

__global__ void __launch_bounds__(256) fftk(const float* __restrict__ Wr,
                                            const float* __restrict__ Wi,
                                            const float* __restrict__ csc) {
    const int bc = blockIdx.y;
    const int b = bc / HIDDEN, c = bc % HIDDEN;
    __shared__ float2 S[PP * PF];
    const int t = threadIdx.x;
    if (t < PP * PF) {
        int ky = t / PF, kx = t % PF;
        float mask = expf(-(float)(ky * ky + kx * kx) * (1.f / 18.f));
        float boost = 1.f + mask * (csc[c] * (0.5f + g_mod[b]));
        float sc = boost * (1.f / 64.f);
        S[t] = make_float2(Wr[c * 40 + t] * sc, Wi[c * 40 + t] * sc);
    }
    __syncthreads();

    const int p = blockIdx.x * 256 + t;
    float* base = g_feat + (((size_t)bc) << 16) + (p >> 5) * (PP * WIDTH) + (p & 31) * PP;

    float2 F[5][8];
#pragma unroll
    for (int y = 0; y < 8; y++) {
        float4 r0 = *(const float4*)(base + y * WIDTH);
        float4 r1 = *(const float4*)(base + y * WIDTH + 4);
        float2 o5[5];
        rfft8(r0, r1, o5);
#pragma unroll
        for (int k = 0; k < 5; k++) F[k][y] = o5[k];
    }
#pragma unroll
    for (int k = 0; k < 5; k++) cfft8<-1>(F[k]);
#pragma unroll
    for (int k = 0; k < 5; k++)
#pragma unroll
        for (int ky = 0; ky < 8; ky++)
            F[k][ky] = cmul(F[k][ky], S[ky * PF + k]);
#pragma unroll
    for (int k = 0; k < 5; k++) cfft8<1>(F[k]);
#pragma unroll
    for (int y = 0; y < 8; y++) {
        float2 z[8];
        z[0] = make_float2(F[0][y].x, 0.f);
        z[1] = F[1][y]; z[2] = F[2][y]; z[3] = F[3][y];
        z[4] = make_float2(F[4][y].x, 0.f);
        z[5] = make_float2(F[3][y].x, -F[3][y].y);
        z[6] = make_float2(F[2][y].x, -F[2][y].y);
        z[7] = make_float2(F[1][y].x, -F[1][y].y);
        cfft8<1>(z);
        *(float4*)(base + y * WIDTH)     = make_float4(z[0].x, z[1].x, z[2].x, z[3].x);
        *(float4*)(base + y * WIDTH + 4) = make_float4(z[4].x, z[5].x, z[6].x, z[7].x);
    }
}

// ================= launch =================
extern "C" void kernel_launch(void* const* d_in, const int* in_sizes, int n_in,
                              void* d_out, int out_size) {
    const float* x     = (const float*)d_in[0];
    const float* w_in  = (const float*)d_in[1];
    const float* w_dw  = (const float*)d_in[2];
    const float* w_out = (const float*)d_in[3];
    const float* Wr    = (const float*)d_in[4];
    const float* Wi    = (const float*)d_in[5];
    const float* csc   = (const float*)d_in[6];
    const float* wm1   = (const float*)d_in[7];
    const float* wm2   = (const float*)d_in[8];
    float* out = (float*)d_out;

    cudaFuncSetAttribute(gemm1_tc, cudaFuncAttributeMaxDynamicSharedMemorySize, 82944);
    cudaFuncSetAttribute(gemm2_tc, cudaFuncAttributeMaxDynamicSharedMemorySize, 110592);

    wsplit<<<96, 256>>>(w_in, w_out);
    gemm1_tc<<<dim3(512, BATCH), 256, 82944>>>(x);
    noop<<<1, 32>>>();
    dwk<<<dim3(2, 8, BATCH * HIDDEN), 256>>>(w_dw);         // launch index 3 -> ncu window
    modk<<<BATCH, 256>>>(wm1, wm2);
    fftk<<<dim3(4, BATCH * HIDDEN), 256>>>(Wr, Wi, csc);
    gemm2_tc<<<dim3(512, BATCH), 256, 110592>>>(out);
}

// round 14
// speedup vs baseline: 1.0660x; 1.0176x over previous
#include <cuda_runtime.h>
#include <cuda_bf16.h>
#include <math.h>
#include <cstdint>

// ---------------- constants ----------------
#define BATCH   4
#define DIM     64
#define HIDDEN  170
#define C2      340           // 2*HIDDEN
#define HW      65536         // 256*256
#define WIDTH   256
#define PP      8
#define PF      5
#define PARTS   16            // gap partials per (b,c)

// ---------------- scratch (device globals; no allocation allowed) ----------------
__device__ float g_xin [(size_t)BATCH * C2 * HW];      // 356 MB
__device__ float g_feat[(size_t)BATCH * HIDDEN * HW];  // 178 MB (feat, then spatial in-place)
__device__ float g_part[BATCH * HIDDEN * PARTS];
__device__ float g_mod [BATCH];
__device__ __nv_bfloat16 g_w1s[2][384][64];            // w_in  split: [hi/lo][o pad][k]
__device__ __nv_bfloat16 g_w2s[2][64][176];            // w_out split: [hi/lo][o][k pad]

// ---------------- helpers ----------------
__device__ __forceinline__ uint32_t smem_u32(const void* p) {
    uint32_t a;
    asm("{ .reg .u64 t; cvta.to.shared.u64 t, %1; cvt.u32.u64 %0, t; }" : "=r"(a) : "l"(p));
    return a;
}
__device__ __forceinline__ uint32_t pack2(float a, float b) {
    uint32_t r;
    asm("cvt.rn.bf16x2.f32 %0, %1, %2;" : "=r"(r) : "f"(b), "f"(a));
    return r;
}
__device__ __forceinline__ void split4(float v0, float v1, float v2, float v3,
                                       uint2& hi, uint2& lo) {
    uint32_t h01 = pack2(v0, v1), h23 = pack2(v2, v3);
    float f0 = __uint_as_float(h01 << 16),  f1 = __uint_as_float(h01 & 0xffff0000u);
    float f2 = __uint_as_float(h23 << 16),  f3 = __uint_as_float(h23 & 0xffff0000u);
    hi = make_uint2(h01, h23);
    lo = make_uint2(pack2(v0 - f0, v1 - f1), pack2(v2 - f2, v3 - f3));
}

__device__ __forceinline__ void mma16816(float d[4], const uint32_t a[4], const uint32_t b[2]) {
    asm volatile(
        "mma.sync.aligned.m16n8k16.row.col.f32.bf16.bf16.f32 "
        "{%0,%1,%2,%3}, {%4,%5,%6,%7}, {%8,%9}, {%0,%1,%2,%3};"
        : "+f"(d[0]), "+f"(d[1]), "+f"(d[2]), "+f"(d[3])
        : "r"(a[0]), "r"(a[1]), "r"(a[2]), "r"(a[3]), "r"(b[0]), "r"(b[1]));
}
__device__ __forceinline__ void ldsm4(uint32_t* r, uint32_t addr) {
    asm volatile("ldmatrix.sync.aligned.m8n8.x4.shared.b16 {%0,%1,%2,%3}, [%4];"
        : "=r"(r[0]), "=r"(r[1]), "=r"(r[2]), "=r"(r[3]) : "r"(addr));
}

// smem tile layout: [ktile][row][16 bf16 = 32B], bit-4 XOR swizzle on (row>>2)&1
__device__ __forceinline__ uint32_t tile_addr(int ktile, int row, int kin2bytes, int kstride) {
    return (uint32_t)(ktile * kstride + ((row * 32 + kin2bytes) ^ (((row >> 2) & 1) << 4)));
}
__device__ __forceinline__ uint32_t row_addr(int row, int byte16) {
    return (uint32_t)((row * 32 + byte16) ^ (((row >> 2) & 1) << 4));
}

// ================= K0: weight split prep =================
__global__ void __launch_bounds__(256) wsplit(const float* __restrict__ w_in,
                                              const float* __restrict__ w_out) {
    int i = blockIdx.x * 256 + threadIdx.x;
    if (i < 384 * 64) {
        int o = i >> 6, k = i & 63;
        float v = (o < C2) ? w_in[o * 64 + k] : 0.f;
        __nv_bfloat16 h = __float2bfloat16(v);
        g_w1s[0][o][k] = h;
        g_w1s[1][o][k] = __float2bfloat16(v - __bfloat162float(h));
    }
    if (i < 64 * 176) {
        int o = i / 176, k = i - o * 176;
        float v = (k < HIDDEN) ? w_out[o * HIDDEN + k] : 0.f;
        __nv_bfloat16 h = __float2bfloat16(v);
        g_w2s[0][o][k] = h;
        g_w2s[1][o][k] = __float2bfloat16(v - __bfloat162float(h));
    }
}

__global__ void noop() {}

// ================= K1: x_in = w_in @ x via mma.sync =================
// A-hi hoisted, B double-buffered (LDG/STS overlap with MMA)
// smem: A 32KB | B 2x16KB | stg 33KB = 97KB -> 2 blocks/SM
__device__ __forceinline__ void g1_fillB(char* buf, int oc, int t) {
#pragma unroll
    for (int i = 0; i < 8; i++) {
        int idx = t + i * 256;
        int pl = idx >> 10;                    // 0..1
        int r  = idx & 1023;
        int o = r >> 4, k = (r & 15) * 4;
        uint2 v = *(const uint2*)&g_w1s[pl][oc * 64 + o][k];
        *(uint2*)(buf + tile_addr(pl * 4 + (k >> 4), o, (k & 15) * 2, 2048)) = v;
    }
}

__global__ void __launch_bounds__(256, 2) gemm1_tc(const float* __restrict__ x) {
    extern __shared__ char smem[];
    char* As  = smem;                              // 32768
    char* Bs0 = smem + 32768;                      // 2 x 16384
    float* stg = (float*)(smem + 65536);           // 33792
    const uint32_t As_u = smem_u32(As);
    const uint32_t Bs_u0 = As_u + 32768;
    const int t = threadIdx.x, lane = t & 31, w = t >> 5;
    const int g = lane >> 2, q = lane & 3;
    const int b = blockIdx.y, pos0 = blockIdx.x * 128;
    const int wy = w & 3, wx = w >> 2;             // 4 pos-warps x 2 o-warps

    uint32_t a_off[2];
#pragma unroll
    for (int mt = 0; mt < 2; mt++)
        a_off[mt] = row_addr(wy * 32 + mt * 16 + (lane & 15), (lane & 16) ? 16 : 0);
    uint32_t b_off[2];
#pragma unroll
    for (int np = 0; np < 2; np++)
        b_off[np] = row_addr(wx * 32 + np * 16 + ((lane >> 4) & 1) * 8 + (lane & 7),
                             (lane & 8) ? 16 : 0);

    // fill B chunk 0 into buffer 0 (latency overlapped with x staging below)
    g1_fillB(Bs0, 0, t);

    // stage x tile [64c][128pos] f32
    const float* xb = x + ((size_t)b * 64) * HW + pos0;
#pragma unroll
    for (int i = 0; i < 8; i++) {
        int idx = t + i * 256, cc = idx >> 5, p4 = idx & 31;
        *(float4*)&stg[cc * 128 + p4 * 4] = *(const float4*)(xb + (size_t)cc * HW + p4 * 4);
    }
    __syncthreads();
    // convert A -> bf16 hi (ktiles 0..3) / lo (4..7)
#pragma unroll
    for (int i = 0; i < 8; i++) {
        int idx = t + i * 256;
        int pos = idx & 127, k = (idx >> 7) * 4;
        float v0 = stg[(k + 0) * 128 + pos], v1 = stg[(k + 1) * 128 + pos];
        float v2 = stg[(k + 2) * 128 + pos], v3 = stg[(k + 3) * 128 + pos];
        uint2 hi, lo; split4(v0, v1, v2, v3, hi, lo);
        uint32_t ah = tile_addr(k >> 4, pos, (k & 15) * 2, 4096);
        *(uint2*)(As + ah) = hi;
        *(uint2*)(As + ah + 4 * 4096) = lo;
    }
    __syncthreads();   // A + B0 visible

    // hoist A-hi fragments
    uint32_t ahi[4][2][4];
#pragma unroll
    for (int at = 0; at < 4; at++) {
        ldsm4(ahi[at][0], As_u + at * 4096 + a_off[0]);
        ldsm4(ahi[at][1], As_u + at * 4096 + a_off[1]);
    }

    for (int oc = 0; oc < 6; oc++) {
        const uint32_t Bcur = Bs_u0 + (uint32_t)(oc & 1) * 16384;
        // prefetch next B chunk into the other buffer (overlaps with MMA below;
        // visibility to next mainloop is guaranteed by the epilogue barriers)
        if (oc < 5) g1_fillB(Bs0 + ((oc + 1) & 1) * 16384, oc + 1, t);

        float acc[2][4][4];
#pragma unroll
        for (int m = 0; m < 2; m++)
#pragma unroll
            for (int n = 0; n < 4; n++)
#pragma unroll
                for (int j = 0; j < 4; j++) acc[m][n][j] = 0.f;

#pragma unroll
        for (int s = 0; s < 12; s++) {
            int bt = (s < 4) ? s : s - 4;    // B: hi,hi,lo
            uint32_t alo[2][4], bf[2][4];
            const uint32_t (*af)[4];
            if (s >= 4 && s < 8) {           // A-lo ktiles 4..7
                ldsm4(alo[0], As_u + s * 4096 + a_off[0]);
                ldsm4(alo[1], As_u + s * 4096 + a_off[1]);
                af = alo;
            } else {
                af = ahi[(s < 4) ? s : s - 8];
            }
            ldsm4(bf[0], Bcur + bt * 2048 + b_off[0]);
            ldsm4(bf[1], Bcur + bt * 2048 + b_off[1]);
#pragma unroll
            for (int np = 0; np < 2; np++)
#pragma unroll
                for (int h = 0; h < 2; h++) {
                    mma16816(acc[0][np * 2 + h], af[0], &bf[np][h * 2]);
                    mma16816(acc[1][np * 2 + h], af[1], &bf[np][h * 2]);
                }
        }

        // stage acc -> smem [o][pos] with 132-float padded rows
        __syncthreads();
#pragma unroll
        for (int mt = 0; mt < 2; mt++)
#pragma unroll
            for (int nt = 0; nt < 4; nt++) {
                int ol = wx * 32 + nt * 8 + q * 2;
                int pl = wy * 32 + mt * 16 + g;
                stg[ol * 132 + pl]           = acc[mt][nt][0];
                stg[(ol + 1) * 132 + pl]     = acc[mt][nt][1];
                stg[ol * 132 + pl + 8]       = acc[mt][nt][2];
                stg[(ol + 1) * 132 + pl + 8] = acc[mt][nt][3];
            }
        __syncthreads();
        // coalesced store: 64 o-rows x 128 pos
#pragma unroll
        for (int i = 0; i < 8; i++) {
            int idx = t + i * 256, o = idx >> 5, p4 = idx & 31;
            int og = oc * 64 + o;
            if (og < C2) {
                float4 v = *(float4*)&stg[o * 132 + p4 * 4];
                *(float4*)&g_xin[((size_t)(b * C2 + og)) * HW + pos0 + p4 * 4] = v;
            }
        }
    }
}

// ================= K5: out = w_out @ spatial via mma.sync (ldmatrix fragments) =================
__global__ void __launch_bounds__(256, 2) gemm2_tc(float* __restrict__ out) {
    extern __shared__ char smem[];
    char* Bs = smem;                       // 22 * 2048 = 45056
    char* As = smem + 45056;               // 8 * 4096  = 32768
    float* stg = (float*)(smem + 45056 + 32768);
    const uint32_t As_u = smem_u32(As), Bs_u = smem_u32(Bs);
    const int t = threadIdx.x, lane = t & 31, w = t >> 5;
    const int g = lane >> 2, q = lane & 3;
    const int b = blockIdx.y, pos0 = blockIdx.x * 128;
    const int wy = w & 3, wx = w >> 2;

    uint32_t a_off[2];
#pragma unroll
    for (int mt = 0; mt < 2; mt++)
        a_off[mt] = row_addr(wy * 32 + mt * 16 + (lane & 15), (lane & 16) ? 16 : 0);
    uint32_t b_off[2];
#pragma unroll
    for (int np = 0; np < 2; np++)
        b_off[np] = row_addr(wx * 32 + np * 16 + ((lane >> 4) & 1) * 8 + (lane & 7),
                             (lane & 8) ? 16 : 0);

    for (int i = t; i < 2 * 64 * 44; i += 256) {
        int pl = i / (64 * 44), r = i - pl * (64 * 44);
        int o = r / 44, k = (r - o * 44) * 4;
        uint2 v = *(const uint2*)&g_w2s[pl][o][k];
        *(uint2*)(Bs + tile_addr(pl * 11 + (k >> 4), o, (k & 15) * 2, 2048)) = v;
    }

    float acc[2][4][4];
#pragma unroll
    for (int m = 0; m < 2; m++)
#pragma unroll
        for (int n = 0; n < 4; n++)
#pragma unroll
            for (int j = 0; j < 4; j++) acc[m][n][j] = 0.f;

    for (int chunk = 0; chunk < 3; chunk++) {
        const int c0 = chunk * 64;
        const int nk = (chunk == 2) ? 3 : 4;
        __syncthreads();
#pragma unroll
        for (int i = 0; i < 8; i++) {
            int idx = t + i * 256, cc = idx >> 5, p4 = idx & 31;
            int c = c0 + cc;
            float4 v = make_float4(0.f, 0.f, 0.f, 0.f);
            if (c < HIDDEN)
                v = *(const float4*)&g_feat[((size_t)(b * HIDDEN + c)) * HW + pos0 + p4 * 4];
            *(float4*)&stg[cc * 128 + p4 * 4] = v;
        }
        __syncthreads();
#pragma unroll
        for (int i = 0; i < 8; i++) {
            int idx = t + i * 256;
            int pos = idx & 127, kk = (idx >> 7) * 4;
            float v0 = stg[(kk + 0) * 128 + pos], v1 = stg[(kk + 1) * 128 + pos];
            float v2 = stg[(kk + 2) * 128 + pos], v3 = stg[(kk + 3) * 128 + pos];
            uint2 hi, lo; split4(v0, v1, v2, v3, hi, lo);
            uint32_t ah = tile_addr(kk >> 4, pos, (kk & 15) * 2, 4096);
            *(uint2*)(As + ah) = hi;
            *(uint2*)(As + ah + 4 * 4096) = lo;
        }
        __syncthreads();

#pragma unroll
        for (int j = 0; j < 4; j++) {
            if (j >= nk) break;
            uint32_t ah2[2][4], al2[2][4], bh[2][4], bl[2][4];
            ldsm4(ah2[0], As_u + j * 4096 + a_off[0]);
            ldsm4(ah2[1], As_u + j * 4096 + a_off[1]);
            ldsm4(al2[0], As_u + (4 + j) * 4096 + a_off[0]);
            ldsm4(al2[1], As_u + (4 + j) * 4096 + a_off[1]);
            ldsm4(bh[0], Bs_u + (4 * chunk + j) * 2048 + b_off[0]);
            ldsm4(bh[1], Bs_u + (4 * chunk + j) * 2048 + b_off[1]);
            ldsm4(bl[0], Bs_u + (11 + 4 * chunk + j) * 2048 + b_off[0]);
            ldsm4(bl[1], Bs_u + (11 + 4 * chunk + j) * 2048 + b_off[1]);
#pragma unroll
            for (int np = 0; np < 2; np++)
#pragma unroll
                for (int h = 0; h < 2; h++) {
                    int nt = np * 2 + h;
                    mma16816(acc[0][nt], ah2[0], &bh[np][h * 2]);
                    mma16816(acc[1][nt], ah2[1], &bh[np][h * 2]);
                    mma16816(acc[0][nt], al2[0], &bh[np][h * 2]);
                    mma16816(acc[1][nt], al2[1], &bh[np][h * 2]);
                    mma16816(acc[0][nt], ah2[0], &bl[np][h * 2]);
                    mma16816(acc[1][nt], ah2[1], &bl[np][h * 2]);
                }
        }
    }

#pragma unroll
    for (int mt = 0; mt < 2; mt++)
#pragma unroll
        for (int nt = 0; nt < 4; nt++) {
            int o = wx * 32 + nt * 8 + q * 2;
            int pos = pos0 + wy * 32 + mt * 16 + g;
            float* p = out + ((size_t)(b * 64 + o)) * HW + pos;
            p[0]      = acc[mt][nt][0];
            p[HW]     = acc[mt][nt][1];
            p[8]      = acc[mt][nt][2];
            p[HW + 8] = acc[mt][nt][3];
        }
}

// ================= K2: depthwise 3x3 + gelu gate + gap partials =================
__device__ __forceinline__ float gelu_exact(float x) {
    return 0.5f * x * (1.f + erff(x * 0.70710678118654752f));
}

template <bool EDGE>
__device__ __forceinline__ void dwk_conv(const float* __restrict__ bp,
                                         const float* __restrict__ wt,
                                         int h0, int w0, int tx, float acc[2][8]) {
    float k[9];
#pragma unroll
    for (int j = 0; j < 9; j++) k[j] = __ldg(wt + j);

#pragma unroll
    for (int r = 0; r < 4; r++) {
        const int gh = h0 - 1 + r;
        const float* row = bp + gh * WIDTH + w0;
        float4 m0, m1;
        bool ok = true;
        if (EDGE) {
            ok = (gh >= 0) && (gh <= 255);
            m0 = make_float4(0.f, 0.f, 0.f, 0.f);
            m1 = make_float4(0.f, 0.f, 0.f, 0.f);
            if (ok) { m0 = *(const float4*)row; m1 = *(const float4*)(row + 4); }
        } else {
            m0 = *(const float4*)row;
            m1 = *(const float4*)(row + 4);
        }
        float lft = __shfl_up_sync(0xffffffffu, m1.w, 1);
        float rgt = __shfl_down_sync(0xffffffffu, m0.x, 1);
        if (tx == 0)  lft = (ok && w0 > 0)   ? __ldg(row - 1) : 0.f;
        if (tx == 15) rgt = (ok && w0 < 248) ? __ldg(row + 8) : 0.f;
        float v[10] = {lft, m0.x, m0.y, m0.z, m0.w, m1.x, m1.y, m1.z, m1.w, rgt};
        if (r < 3) {
            float c0 = k[r * 3], c1 = k[r * 3 + 1], c2 = k[r * 3 + 2];
#pragma unroll
            for (int j = 0; j < 8; j++)
                acc[0][j] += c0 * v[j] + c1 * v[j + 1] + c2 * v[j + 2];
        }
        if (r >= 1) {
            float c0 = k[(r - 1) * 3], c1 = k[(r - 1) * 3 + 1], c2 = k[(r - 1) * 3 + 2];
#pragma unroll
            for (int j = 0; j < 8; j++)
                acc[1][j] += c0 * v[j] + c1 * v[j + 1] + c2 * v[j + 2];
        }
    }
}

__global__ void __launch_bounds__(256) dwk(const float* __restrict__ w_dw) {
    const int bc = blockIdx.z;
    const int b = bc / HIDDEN, c = bc % HIDDEN;
    const int t = threadIdx.x;
    const int tx = t & 15, ty = t >> 4;
    const int w0 = blockIdx.x * 128 + tx * 8;
    const int h0 = blockIdx.y * 32 + ty * 2;

    float a0[2][8], a1[2][8];
#pragma unroll
    for (int orr = 0; orr < 2; orr++)
#pragma unroll
        for (int j = 0; j < 8; j++) { a0[orr][j] = 0.f; a1[orr][j] = 0.f; }

    const float* bp0 = g_xin + ((size_t)(b * C2 + c)) * HW;
    const float* bp1 = g_xin + ((size_t)(b * C2 + c + HIDDEN)) * HW;
    const float* wt0 = w_dw + c * 9;
    const float* wt1 = w_dw + (c + HIDDEN) * 9;

    if (blockIdx.y == 0 || blockIdx.y == 7) {
        dwk_conv<true>(bp0, wt0, h0, w0, tx, a0);
        dwk_conv<true>(bp1, wt1, h0, w0, tx, a1);
    } else {
        dwk_conv<false>(bp0, wt0, h0, w0, tx, a0);
        dwk_conv<false>(bp1, wt1, h0, w0, tx, a1);
    }

    float s = 0.f;
#pragma unroll
    for (int orr = 0; orr < 2; orr++) {
        float f[8];
#pragma unroll
        for (int j = 0; j < 8; j++) {
            f[j] = gelu_exact(a0[orr][j]) * a1[orr][j];
            s += f[j];
        }
        float* op = g_feat + ((size_t)bc) * HW + (h0 + orr) * WIDTH + w0;
        *(float4*)op       = make_float4(f[0], f[1], f[2], f[3]);
        *(float4*)(op + 4) = make_float4(f[4], f[5], f[6], f[7]);
    }

    __shared__ float red[256];
    red[t] = s;
    __syncthreads();
#pragma unroll
    for (int off = 128; off > 0; off >>= 1) {
        if (t < off) red[t] += red[t + off];
        __syncthreads();
    }
    if (t == 0)
        g_part[bc * PARTS + blockIdx.y * 2 + blockIdx.x] = red[0];
}

// ================= K3: gap reduce + modulation =================
__global__ void __launch_bounds__(256) modk(const float* __restrict__ w_mod1,
                                            const float* __restrict__ w_mod2) {
    const int b = blockIdx.x;
    const int t = threadIdx.x;
    __shared__ float gap_s[HIDDEN];
    __shared__ float relu_s[16];

    for (int c = t; c < HIDDEN; c += 256) {
        const float4* p = (const float4*)(g_part + (size_t)(b * HIDDEN + c) * PARTS);
        float4 s0 = p[0], s1 = p[1], s2 = p[2], s3 = p[3];
        float s = (s0.x + s0.y + s0.z + s0.w) + (s1.x + s1.y + s1.z + s1.w)
                + (s2.x + s2.y + s2.z + s2.w) + (s3.x + s3.y + s3.z + s3.w);
        gap_s[c] = s * (1.f / 65536.f);
    }
    __syncthreads();

    const int wid = t >> 5, lane = t & 31;
    for (int j = wid; j < 10; j += 8) {
        float s = 0.f;
        for (int c = lane; c < HIDDEN; c += 32)
            s += gap_s[c] * w_mod1[j * HIDDEN + c];
#pragma unroll
        for (int off = 16; off > 0; off >>= 1) s += __shfl_xor_sync(0xffffffff, s, off);
        if (lane == 0) relu_s[j] = fmaxf(s, 0.f);
    }
    __syncthreads();
    if (t == 0) {
        float m = 0.f;
#pragma unroll
        for (int j = 0; j < 10; j++) m += relu_s[j] * w_mod2[j];
        g_mod[b] = 1.f / (1.f + expf(-m));
    }
}

// ================= K4: per-patch rfft2 * S -> irfft2 =================
__device__ __forceinline__ float2 cmul(float2 a, float2 b) {
    return make_float2(a.x * b.x - a.y * b.y, a.x * b.y + a.y * b.x);
}
__device__ __forceinline__ float2 cadd(float2 a, float2 b) { return make_float2(a.x + b.x, a.y + b.y); }
__device__ __forceinline__ float2 csub(float2 a, float2 b) { return make_float2(a.x - b.x, a.y - b.y); }

template <int SIGN>
__device__ __forceinline__ void cfft8(float2 x[8]) {
    float2 e0 = x[0], e1 = x[2], e2 = x[4], e3 = x[6];
    float2 o0 = x[1], o1 = x[3], o2 = x[5], o3 = x[7];
    float2 t0 = cadd(e0, e2), t1 = csub(e0, e2), t2 = cadd(e1, e3), t3 = csub(e1, e3);
    float2 rt3 = (SIGN < 0) ? make_float2(t3.y, -t3.x) : make_float2(-t3.y, t3.x);
    float2 E0 = cadd(t0, t2), E2 = csub(t0, t2), E1 = cadd(t1, rt3), E3 = csub(t1, rt3);
    t0 = cadd(o0, o2); t1 = csub(o0, o2); t2 = cadd(o1, o3); t3 = csub(o1, o3);
    rt3 = (SIGN < 0) ? make_float2(t3.y, -t3.x) : make_float2(-t3.y, t3.x);
    float2 O0 = cadd(t0, t2), O2 = csub(t0, t2), O1 = cadd(t1, rt3), O3 = csub(t1, rt3);
    const float s = 0.70710678118654752f;
    const float2 w1 = make_float2(s, (SIGN < 0) ? -s : s);
    const float2 w2 = make_float2(0.f, (SIGN < 0) ? -1.f : 1.f);
    const float2 w3 = make_float2(-s, (SIGN < 0) ? -s : s);
    float2 a;
    a = O0;           x[0] = cadd(E0, a); x[4] = csub(E0, a);
    a = cmul(w1, O1); x[1] = cadd(E1, a); x[5] = csub(E1, a);
    a = cmul(w2, O2); x[2] = cadd(E2, a); x[6] = csub(E2, a);
    a = cmul(w3, O3); x[3] = cadd(E3, a); x[7] = csub(E3, a);
}

__device__ __forceinline__ void rfft8(float4 r0, float4 r1, float2 out[5]) {
    float e0 = r0.x, e1 = r0.z, e2 = r1.x, e3 = r1.z;
    float o0 = r0.y, o1 = r0.w, o2 = r1.y, o3 = r1.w;
    float ep = e0 + e2, em = e0 - e2, eq = e1 + e3, er = e1 - e3;
    float op = o0 + o2, om = o0 - o2, oq = o1 + o3, orr = o1 - o3;
    float E0 = ep + eq, E2 = ep - eq;
    float O0 = op + oq, O2 = op - oq;
    const float s = 0.70710678118654752f;
    float w1x = s * (om - orr), w1y = s * (-orr - om);
    float w3x = s * (orr - om), w3y = -s * (om + orr);
    out[0] = make_float2(E0 + O0, 0.f);
    out[1] = make_float2(em + w1x, -er + w1y);
    out[2] = make_float2(E2, -O2);
    out[3] = make_float2(em + w3x, er + w3y);
    out[4] = make_float2(E0 - O0, 0.f);
}

__global__ void __launch_bounds__(256, 3) fftk(const float* __restrict__ Wr,
                                               const float* __restrict__ Wi,
                                               const float* __restrict__ csc) {
    const int bc = blockIdx.y;
    const int b = bc / HIDDEN, c = bc % HIDDEN;
    __shared__ float2 S[PP * PF];
    const int t = threadIdx.x;
    if (t < PP * PF) {
        int ky = t / PF, kx = t % PF;
        float mask = expf(-(float)(ky * ky + kx * kx) * (1.f / 18.f));
        float boost = 1.f + mask * (csc[c] * (0.5f + g_mod[b]));
        float sc = boost * (1.f / 64.f);
        S[t] = make_float2(Wr[c * 40 + t] * sc, Wi[c * 40 + t] * sc);
    }
    __syncthreads();

    const int p = blockIdx.x * 256 + t;
    float* base = g_feat + (((size_t)bc) << 16) + (p >> 5) * (PP * WIDTH) + (p & 31) * PP;

    float2 F[5][8];
#pragma unroll
    for (int y = 0; y < 8; y++) {
        float4 r0 = *(const float4*)(base + y * WIDTH);
        float4 r1 = *(const float4*)(base + y * WIDTH + 4);
        float2 o5[5];
        rfft8(r0, r1, o5);
#pragma unroll
        for (int k = 0; k < 5; k++) F[k][y] = o5[k];
    }
#pragma unroll
    for (int k = 0; k < 5; k++) cfft8<-1>(F[k]);
#pragma unroll
    for (int k = 0; k < 5; k++)
#pragma unroll
        for (int ky = 0; ky < 8; ky++)
            F[k][ky] = cmul(F[k][ky], S[ky * PF + k]);
#pragma unroll
    for (int k = 0; k < 5; k++) cfft8<1>(F[k]);
#pragma unroll
    for (int y = 0; y < 8; y++) {
        float2 z[8];
        z[0] = make_float2(F[0][y].x, 0.f);
        z[1] = F[1][y]; z[2] = F[2][y]; z[3] = F[3][y];
        z[4] = make_float2(F[4][y].x, 0.f);
        z[5] = make_float2(F[3][y].x, -F[3][y].y);
        z[6] = make_float2(F[2][y].x, -F[2][y].y);
        z[7] = make_float2(F[1][y].x, -F[1][y].y);
        cfft8<1>(z);
        *(float4*)(base + y * WIDTH)     = make_float4(z[0].x, z[1].x, z[2].x, z[3].x);
        *(float4*)(base + y * WIDTH + 4) = make_float4(z[4].x, z[5].x, z[6].x, z[7].x);
    }
}

// ================= launch =================
extern "C" void kernel_launch(void* const* d_in, const int* in_sizes, int n_in,
                              void* d_out, int out_size) {
    const float* x     = (const float*)d_in[0];
    const float* w_in  = (const float*)d_in[1];
    const float* w_dw  = (const float*)d_in[2];
    const float* w_out = (const float*)d_in[3];
    const float* Wr    = (const float*)d_in[4];
    const float* Wi    = (const float*)d_in[5];
    const float* csc   = (const float*)d_in[6];
    const float* wm1   = (const float*)d_in[7];
    const float* wm2   = (const float*)d_in[8];
    float* out = (float*)d_out;

    cudaFuncSetAttribute(gemm1_tc, cudaFuncAttributeMaxDynamicSharedMemorySize, 99328);
    cudaFuncSetAttribute(gemm2_tc, cudaFuncAttributeMaxDynamicSharedMemorySize, 110592);

    wsplit<<<96, 256>>>(w_in, w_out);
    noop<<<1, 32>>>();
    noop<<<1, 32>>>();
    gemm1_tc<<<dim3(512, BATCH), 256, 99328>>>(x);          // launch index 3 -> ncu window
    dwk<<<dim3(2, 8, BATCH * HIDDEN), 256>>>(w_dw);
    modk<<<BATCH, 256>>>(wm1, wm2);
    fftk<<<dim3(4, BATCH * HIDDEN), 256>>>(Wr, Wi, csc);
    gemm2_tc<<<dim3(512, BATCH), 256, 110592>>>(out);
}

// round 17
// speedup vs baseline: 1.0745x; 1.0079x over previous
#include <cuda_runtime.h>
#include <cuda_bf16.h>
#include <math.h>
#include <cstdint>

// ---------------- constants ----------------
#define BATCH   4
#define DIM     64
#define HIDDEN  170
#define C2      340           // 2*HIDDEN
#define HW      65536         // 256*256
#define WIDTH   256
#define PP      8
#define PF      5
#define PARTS   16            // gap partials per (b,c)

// ---------------- scratch (device globals; no allocation allowed) ----------------
__device__ float g_xin [(size_t)BATCH * C2 * HW];      // 356 MB
__device__ float g_feat[(size_t)BATCH * HIDDEN * HW];  // 178 MB (feat, then spatial in-place)
__device__ float g_part[BATCH * HIDDEN * PARTS];
__device__ float g_mod [BATCH];
__device__ __nv_bfloat16 g_w1s[2][384][64];            // w_in  split: [hi/lo][o pad][k]
__device__ __nv_bfloat16 g_w2s[2][64][176];            // w_out split: [hi/lo][o][k pad]

// ---------------- helpers ----------------
__device__ __forceinline__ uint32_t smem_u32(const void* p) {
    uint32_t a;
    asm("{ .reg .u64 t; cvta.to.shared.u64 t, %1; cvt.u32.u64 %0, t; }" : "=r"(a) : "l"(p));
    return a;
}
__device__ __forceinline__ uint32_t pack2(float a, float b) {
    uint32_t r;
    asm("cvt.rn.bf16x2.f32 %0, %1, %2;" : "=r"(r) : "f"(b), "f"(a));
    return r;
}
__device__ __forceinline__ void split4(float v0, float v1, float v2, float v3,
                                       uint2& hi, uint2& lo) {
    uint32_t h01 = pack2(v0, v1), h23 = pack2(v2, v3);
    float f0 = __uint_as_float(h01 << 16),  f1 = __uint_as_float(h01 & 0xffff0000u);
    float f2 = __uint_as_float(h23 << 16),  f3 = __uint_as_float(h23 & 0xffff0000u);
    hi = make_uint2(h01, h23);
    lo = make_uint2(pack2(v0 - f0, v1 - f1), pack2(v2 - f2, v3 - f3));
}

__device__ __forceinline__ void mma16816(float d[4], const uint32_t a[4], const uint32_t b[2]) {
    asm volatile(
        "mma.sync.aligned.m16n8k16.row.col.f32.bf16.bf16.f32 "
        "{%0,%1,%2,%3}, {%4,%5,%6,%7}, {%8,%9}, {%0,%1,%2,%3};"
        : "+f"(d[0]), "+f"(d[1]), "+f"(d[2]), "+f"(d[3])
        : "r"(a[0]), "r"(a[1]), "r"(a[2]), "r"(a[3]), "r"(b[0]), "r"(b[1]));
}
__device__ __forceinline__ void ldsm4(uint32_t* r, uint32_t addr) {
    asm volatile("ldmatrix.sync.aligned.m8n8.x4.shared.b16 {%0,%1,%2,%3}, [%4];"
        : "=r"(r[0]), "=r"(r[1]), "=r"(r[2]), "=r"(r[3]) : "r"(addr));
}

// smem tile layout: [ktile][row][16 bf16 = 32B], bit-4 XOR swizzle on (row>>2)&1
__device__ __forceinline__ uint32_t tile_addr(int ktile, int row, int kin2bytes, int kstride) {
    return (uint32_t)(ktile * kstride + ((row * 32 + kin2bytes) ^ (((row >> 2) & 1) << 4)));
}
__device__ __forceinline__ uint32_t row_addr(int row, int byte16) {
    return (uint32_t)((row * 32 + byte16) ^ (((row >> 2) & 1) << 4));
}

// ================= K0: weight split prep =================
__global__ void __launch_bounds__(256) wsplit(const float* __restrict__ w_in,
                                              const float* __restrict__ w_out) {
    int i = blockIdx.x * 256 + threadIdx.x;
    if (i < 384 * 64) {
        int o = i >> 6, k = i & 63;
        float v = (o < C2) ? w_in[o * 64 + k] : 0.f;
        __nv_bfloat16 h = __float2bfloat16(v);
        g_w1s[0][o][k] = h;
        g_w1s[1][o][k] = __float2bfloat16(v - __bfloat162float(h));
    }
    if (i < 64 * 176) {
        int o = i / 176, k = i - o * 176;
        float v = (k < HIDDEN) ? w_out[o * HIDDEN + k] : 0.f;
        __nv_bfloat16 h = __float2bfloat16(v);
        g_w2s[0][o][k] = h;
        g_w2s[1][o][k] = __float2bfloat16(v - __bfloat162float(h));
    }
}

__global__ void noop() {}

// ================= K1: x_in = w_in @ x via mma.sync =================
// A-hi hoisted, B double-buffered, DIRECT sector-coalesced STG epilogue
// smem: A 32KB | B 2x16KB | stg 32KB = 96KB -> 2 blocks/SM
__device__ __forceinline__ void g1_fillB(char* buf, int oc, int t) {
#pragma unroll
    for (int i = 0; i < 8; i++) {
        int idx = t + i * 256;
        int pl = idx >> 10;                    // 0..1
        int r  = idx & 1023;
        int o = r >> 4, k = (r & 15) * 4;
        uint2 v = *(const uint2*)&g_w1s[pl][oc * 64 + o][k];
        *(uint2*)(buf + tile_addr(pl * 4 + (k >> 4), o, (k & 15) * 2, 2048)) = v;
    }
}

__global__ void __launch_bounds__(256, 2) gemm1_tc(const float* __restrict__ x) {
    extern __shared__ char smem[];
    char* As  = smem;                              // 32768
    char* Bs0 = smem + 32768;                      // 2 x 16384
    float* stg = (float*)(smem + 65536);           // 32768 (x staging only)
    const uint32_t As_u = smem_u32(As);
    const uint32_t Bs_u0 = As_u + 32768;
    const int t = threadIdx.x, lane = t & 31, w = t >> 5;
    const int g = lane >> 2, q = lane & 3;
    const int b = blockIdx.y, pos0 = blockIdx.x * 128;
    const int wy = w & 3, wx = w >> 2;             // 4 pos-warps x 2 o-warps

    uint32_t a_off[2];
#pragma unroll
    for (int mt = 0; mt < 2; mt++)
        a_off[mt] = row_addr(wy * 32 + mt * 16 + (lane & 15), (lane & 16) ? 16 : 0);
    uint32_t b_off[2];
#pragma unroll
    for (int np = 0; np < 2; np++)
        b_off[np] = row_addr(wx * 32 + np * 16 + ((lane >> 4) & 1) * 8 + (lane & 7),
                             (lane & 8) ? 16 : 0);

    // fill B chunk 0 into buffer 0 (latency overlapped with x staging below)
    g1_fillB(Bs0, 0, t);

    // stage x tile [64c][128pos] f32
    const float* xb = x + ((size_t)b * 64) * HW + pos0;
#pragma unroll
    for (int i = 0; i < 8; i++) {
        int idx = t + i * 256, cc = idx >> 5, p4 = idx & 31;
        *(float4*)&stg[cc * 128 + p4 * 4] = *(const float4*)(xb + (size_t)cc * HW + p4 * 4);
    }
    __syncthreads();
    // convert A -> bf16 hi (ktiles 0..3) / lo (4..7)
#pragma unroll
    for (int i = 0; i < 8; i++) {
        int idx = t + i * 256;
        int pos = idx & 127, k = (idx >> 7) * 4;
        float v0 = stg[(k + 0) * 128 + pos], v1 = stg[(k + 1) * 128 + pos];
        float v2 = stg[(k + 2) * 128 + pos], v3 = stg[(k + 3) * 128 + pos];
        uint2 hi, lo; split4(v0, v1, v2, v3, hi, lo);
        uint32_t ah = tile_addr(k >> 4, pos, (k & 15) * 2, 4096);
        *(uint2*)(As + ah) = hi;
        *(uint2*)(As + ah + 4 * 4096) = lo;
    }
    __syncthreads();   // A + B0 visible

    // hoist A-hi fragments
    uint32_t ahi[4][2][4];
#pragma unroll
    for (int at = 0; at < 4; at++) {
        ldsm4(ahi[at][0], As_u + at * 4096 + a_off[0]);
        ldsm4(ahi[at][1], As_u + at * 4096 + a_off[1]);
    }

    const int posg = pos0 + wy * 32 + g;           // this thread's base position

    for (int oc = 0; oc < 6; oc++) {
        const uint32_t Bcur = Bs_u0 + (uint32_t)(oc & 1) * 16384;
        // prefetch next B chunk into the other buffer (overlaps with MMA below)
        if (oc < 5) g1_fillB(Bs0 + ((oc + 1) & 1) * 16384, oc + 1, t);

        float acc[2][4][4];
#pragma unroll
        for (int m = 0; m < 2; m++)
#pragma unroll
            for (int n = 0; n < 4; n++)
#pragma unroll
                for (int j = 0; j < 4; j++) acc[m][n][j] = 0.f;

#pragma unroll
        for (int s = 0; s < 12; s++) {
            int bt = (s < 4) ? s : s - 4;    // B: hi,hi,lo
            uint32_t alo[2][4], bf[2][4];
            const uint32_t (*af)[4];
            if (s >= 4 && s < 8) {           // A-lo ktiles 4..7
                ldsm4(alo[0], As_u + s * 4096 + a_off[0]);
                ldsm4(alo[1], As_u + s * 4096 + a_off[1]);
                af = alo;
            } else {
                af = ahi[(s < 4) ? s : s - 8];
            }
            ldsm4(bf[0], Bcur + bt * 2048 + b_off[0]);
            ldsm4(bf[1], Bcur + bt * 2048 + b_off[1]);
#pragma unroll
            for (int np = 0; np < 2; np++)
#pragma unroll
                for (int h = 0; h < 2; h++) {
                    mma16816(acc[0][np * 2 + h], af[0], &bf[np][h * 2]);
                    mma16816(acc[1][np * 2 + h], af[1], &bf[np][h * 2]);
                }
        }

        // direct sector-coalesced epilogue:
        // per (mt,nt) instruction the warp covers 4 o-rows x 8 consecutive pos -> 4 full 32B sectors
#pragma unroll
        for (int mt = 0; mt < 2; mt++)
#pragma unroll
            for (int nt = 0; nt < 4; nt++) {
                int o = oc * 64 + wx * 32 + nt * 8 + q * 2;     // even
                if (o < C2) {
                    int pos = posg + mt * 16;
                    float* p = g_xin + ((size_t)(b * C2 + o)) * HW + pos;
                    p[0]      = acc[mt][nt][0];
                    p[HW]     = acc[mt][nt][1];
                    p[8]      = acc[mt][nt][2];
                    p[HW + 8] = acc[mt][nt][3];
                }
            }
        __syncthreads();   // prefetched B visible for next chunk; read/write buffer handoff
    }
}

// ================= K5: out = w_out @ spatial via mma.sync (ldmatrix fragments) =================
__global__ void __launch_bounds__(256, 2) gemm2_tc(float* __restrict__ out) {
    extern __shared__ char smem[];
    char* Bs = smem;                       // 22 * 2048 = 45056
    char* As = smem + 45056;               // 8 * 4096  = 32768
    float* stg = (float*)(smem + 45056 + 32768);
    const uint32_t As_u = smem_u32(As), Bs_u = smem_u32(Bs);
    const int t = threadIdx.x, lane = t & 31, w = t >> 5;
    const int g = lane >> 2, q = lane & 3;
    const int b = blockIdx.y, pos0 = blockIdx.x * 128;
    const int wy = w & 3, wx = w >> 2;

    uint32_t a_off[2];
#pragma unroll
    for (int mt = 0; mt < 2; mt++)
        a_off[mt] = row_addr(wy * 32 + mt * 16 + (lane & 15), (lane & 16) ? 16 : 0);
    uint32_t b_off[2];
#pragma unroll
    for (int np = 0; np < 2; np++)
        b_off[np] = row_addr(wx * 32 + np * 16 + ((lane >> 4) & 1) * 8 + (lane & 7),
                             (lane & 8) ? 16 : 0);

    for (int i = t; i < 2 * 64 * 44; i += 256) {
        int pl = i / (64 * 44), r = i - pl * (64 * 44);
        int o = r / 44, k = (r - o * 44) * 4;
        uint2 v = *(const uint2*)&g_w2s[pl][o][k];
        *(uint2*)(Bs + tile_addr(pl * 11 + (k >> 4), o, (k & 15) * 2, 2048)) = v;
    }

    float acc[2][4][4];
#pragma unroll
    for (int m = 0; m < 2; m++)
#pragma unroll
        for (int n = 0; n < 4; n++)
#pragma unroll
            for (int j = 0; j < 4; j++) acc[m][n][j] = 0.f;

    for (int chunk = 0; chunk < 3; chunk++) {
        const int c0 = chunk * 64;
        const int nk = (chunk == 2) ? 3 : 4;
        __syncthreads();
#pragma unroll
        for (int i = 0; i < 8; i++) {
            int idx = t + i * 256, cc = idx >> 5, p4 = idx & 31;
            int c = c0 + cc;
            float4 v = make_float4(0.f, 0.f, 0.f, 0.f);
            if (c < HIDDEN)
                v = *(const float4*)&g_feat[((size_t)(b * HIDDEN + c)) * HW + pos0 + p4 * 4];
            *(float4*)&stg[cc * 128 + p4 * 4] = v;
        }
        __syncthreads();
#pragma unroll
        for (int i = 0; i < 8; i++) {
            int idx = t + i * 256;
            int pos = idx & 127, kk = (idx >> 7) * 4;
            float v0 = stg[(kk + 0) * 128 + pos], v1 = stg[(kk + 1) * 128 + pos];
            float v2 = stg[(kk + 2) * 128 + pos], v3 = stg[(kk + 3) * 128 + pos];
            uint2 hi, lo; split4(v0, v1, v2, v3, hi, lo);
            uint32_t ah = tile_addr(kk >> 4, pos, (kk & 15) * 2, 4096);
            *(uint2*)(As + ah) = hi;
            *(uint2*)(As + ah + 4 * 4096) = lo;
        }
        __syncthreads();

#pragma unroll
        for (int j = 0; j < 4; j++) {
            if (j >= nk) break;
            uint32_t ah2[2][4], al2[2][4], bh[2][4], bl[2][4];
            ldsm4(ah2[0], As_u + j * 4096 + a_off[0]);
            ldsm4(ah2[1], As_u + j * 4096 + a_off[1]);
            ldsm4(al2[0], As_u + (4 + j) * 4096 + a_off[0]);
            ldsm4(al2[1], As_u + (4 + j) * 4096 + a_off[1]);
            ldsm4(bh[0], Bs_u + (4 * chunk + j) * 2048 + b_off[0]);
            ldsm4(bh[1], Bs_u + (4 * chunk + j) * 2048 + b_off[1]);
            ldsm4(bl[0], Bs_u + (11 + 4 * chunk + j) * 2048 + b_off[0]);
            ldsm4(bl[1], Bs_u + (11 + 4 * chunk + j) * 2048 + b_off[1]);
#pragma unroll
            for (int np = 0; np < 2; np++)
#pragma unroll
                for (int h = 0; h < 2; h++) {
                    int nt = np * 2 + h;
                    mma16816(acc[0][nt], ah2[0], &bh[np][h * 2]);
                    mma16816(acc[1][nt], ah2[1], &bh[np][h * 2]);
                    mma16816(acc[0][nt], al2[0], &bh[np][h * 2]);
                    mma16816(acc[1][nt], al2[1], &bh[np][h * 2]);
                    mma16816(acc[0][nt], ah2[0], &bl[np][h * 2]);
                    mma16816(acc[1][nt], ah2[1], &bl[np][h * 2]);
                }
        }
    }

#pragma unroll
    for (int mt = 0; mt < 2; mt++)
#pragma unroll
        for (int nt = 0; nt < 4; nt++) {
            int o = wx * 32 + nt * 8 + q * 2;
            int pos = pos0 + wy * 32 + mt * 16 + g;
            float* p = out + ((size_t)(b * 64 + o)) * HW + pos;
            p[0]      = acc[mt][nt][0];
            p[HW]     = acc[mt][nt][1];
            p[8]      = acc[mt][nt][2];
            p[HW + 8] = acc[mt][nt][3];
        }
}

// ================= K2: depthwise 3x3 + gelu gate + gap partials =================
__device__ __forceinline__ float gelu_exact(float x) {
    return 0.5f * x * (1.f + erff(x * 0.70710678118654752f));
}

template <bool EDGE>
__device__ __forceinline__ void dwk_conv(const float* __restrict__ bp,
                                         const float* __restrict__ wt,
                                         int h0, int w0, int tx, float acc[2][8]) {
    float k[9];
#pragma unroll
    for (int j = 0; j < 9; j++) k[j] = __ldg(wt + j);

#pragma unroll
    for (int r = 0; r < 4; r++) {
        const int gh = h0 - 1 + r;
        const float* row = bp + gh * WIDTH + w0;
        float4 m0, m1;
        bool ok = true;
        if (EDGE) {
            ok = (gh >= 0) && (gh <= 255);
            m0 = make_float4(0.f, 0.f, 0.f, 0.f);
            m1 = make_float4(0.f, 0.f, 0.f, 0.f);
            if (ok) { m0 = *(const float4*)row; m1 = *(const float4*)(row + 4); }
        } else {
            m0 = *(const float4*)row;
            m1 = *(const float4*)(row + 4);
        }
        float lft = __shfl_up_sync(0xffffffffu, m1.w, 1);
        float rgt = __shfl_down_sync(0xffffffffu, m0.x, 1);
        if (tx == 0)  lft = (ok && w0 > 0)   ? __ldg(row - 1) : 0.f;
        if (tx == 15) rgt = (ok && w0 < 248) ? __ldg(row + 8) : 0.f;
        float v[10] = {lft, m0.x, m0.y, m0.z, m0.w, m1.x, m1.y, m1.z, m1.w, rgt};
        if (r < 3) {
            float c0 = k[r * 3], c1 = k[r * 3 + 1], c2 = k[r * 3 + 2];
#pragma unroll
            for (int j = 0; j < 8; j++)
                acc[0][j] += c0 * v[j] + c1 * v[j + 1] + c2 * v[j + 2];
        }
        if (r >= 1) {
            float c0 = k[(r - 1) * 3], c1 = k[(r - 1) * 3 + 1], c2 = k[(r - 1) * 3 + 2];
#pragma unroll
            for (int j = 0; j < 8; j++)
                acc[1][j] += c0 * v[j] + c1 * v[j + 1] + c2 * v[j + 2];
        }
    }
}

__global__ void __launch_bounds__(256) dwk(const float* __restrict__ w_dw) {
    const int bc = blockIdx.z;
    const int b = bc / HIDDEN, c = bc % HIDDEN;
    const int t = threadIdx.x;
    const int tx = t & 15, ty = t >> 4;
    const int w0 = blockIdx.x * 128 + tx * 8;
    const int h0 = blockIdx.y * 32 + ty * 2;

    float a0[2][8], a1[2][8];
#pragma unroll
    for (int orr = 0; orr < 2; orr++)
#pragma unroll
        for (int j = 0; j < 8; j++) { a0[orr][j] = 0.f; a1[orr][j] = 0.f; }

    const float* bp0 = g_xin + ((size_t)(b * C2 + c)) * HW;
    const float* bp1 = g_xin + ((size_t)(b * C2 + c + HIDDEN)) * HW;
    const float* wt0 = w_dw + c * 9;
    const float* wt1 = w_dw + (c + HIDDEN) * 9;

    if (blockIdx.y == 0 || blockIdx.y == 7) {
        dwk_conv<true>(bp0, wt0, h0, w0, tx, a0);
        dwk_conv<true>(bp1, wt1, h0, w0, tx, a1);
    } else {
        dwk_conv<false>(bp0, wt0, h0, w0, tx, a0);
        dwk_conv<false>(bp1, wt1, h0, w0, tx, a1);
    }

    float s = 0.f;
#pragma unroll
    for (int orr = 0; orr < 2; orr++) {
        float f[8];
#pragma unroll
        for (int j = 0; j < 8; j++) {
            f[j] = gelu_exact(a0[orr][j]) * a1[orr][j];
            s += f[j];
        }
        float* op = g_feat + ((size_t)bc) * HW + (h0 + orr) * WIDTH + w0;
        *(float4*)op       = make_float4(f[0], f[1], f[2], f[3]);
        *(float4*)(op + 4) = make_float4(f[4], f[5], f[6], f[7]);
    }

    __shared__ float red[256];
    red[t] = s;
    __syncthreads();
#pragma unroll
    for (int off = 128; off > 0; off >>= 1) {
        if (t < off) red[t] += red[t + off];
        __syncthreads();
    }
    if (t == 0)
        g_part[bc * PARTS + blockIdx.y * 2 + blockIdx.x] = red[0];
}

// ================= K3: gap reduce + modulation =================
__global__ void __launch_bounds__(256) modk(const float* __restrict__ w_mod1,
                                            const float* __restrict__ w_mod2) {
    const int b = blockIdx.x;
    const int t = threadIdx.x;
    __shared__ float gap_s[HIDDEN];
    __shared__ float relu_s[16];

    for (int c = t; c < HIDDEN; c += 256) {
        const float4* p = (const float4*)(g_part + (size_t)(b * HIDDEN + c) * PARTS);
        float4 s0 = p[0], s1 = p[1], s2 = p[2], s3 = p[3];
        float s = (s0.x + s0.y + s0.z + s0.w) + (s1.x + s1.y + s1.z + s1.w)
                + (s2.x + s2.y + s2.z + s2.w) + (s3.x + s3.y + s3.z + s3.w);
        gap_s[c] = s * (1.f / 65536.f);
    }
    __syncthreads();

    const int wid = t >> 5, lane = t & 31;
    for (int j = wid; j < 10; j += 8) {
        float s = 0.f;
        for (int c = lane; c < HIDDEN; c += 32)
            s += gap_s[c] * w_mod1[j * HIDDEN + c];
#pragma unroll
        for (int off = 16; off > 0; off >>= 1) s += __shfl_xor_sync(0xffffffff, s, off);
        if (lane == 0) relu_s[j] = fmaxf(s, 0.f);
    }
    __syncthreads();
    if (t == 0) {
        float m = 0.f;
#pragma unroll
        for (int j = 0; j < 10; j++) m += relu_s[j] * w_mod2[j];
        g_mod[b] = 1.f / (1.f + expf(-m));
    }
}

// ================= K4: per-patch rfft2 * S -> irfft2 =================
__device__ __forceinline__ float2 cmul(float2 a, float2 b) {
    return make_float2(a.x * b.x - a.y * b.y, a.x * b.y + a.y * b.x);
}
__device__ __forceinline__ float2 cadd(float2 a, float2 b) { return make_float2(a.x + b.x, a.y + b.y); }
__device__ __forceinline__ float2 csub(float2 a, float2 b) { return make_float2(a.x - b.x, a.y - b.y); }

template <int SIGN>
__device__ __forceinline__ void cfft8(float2 x[8]) {
    float2 e0 = x[0], e1 = x[2], e2 = x[4], e3 = x[6];
    float2 o0 = x[1], o1 = x[3], o2 = x[5], o3 = x[7];
    float2 t0 = cadd(e0, e2), t1 = csub(e0, e2), t2 = cadd(e1, e3), t3 = csub(e1, e3);
    float2 rt3 = (SIGN < 0) ? make_float2(t3.y, -t3.x) : make_float2(-t3.y, t3.x);
    float2 E0 = cadd(t0, t2), E2 = csub(t0, t2), E1 = cadd(t1, rt3), E3 = csub(t1, rt3);
    t0 = cadd(o0, o2); t1 = csub(o0, o2); t2 = cadd(o1, o3); t3 = csub(o1, o3);
    rt3 = (SIGN < 0) ? make_float2(t3.y, -t3.x) : make_float2(-t3.y, t3.x);
    float2 O0 = cadd(t0, t2), O2 = csub(t0, t2), O1 = cadd(t1, rt3), O3 = csub(t1, rt3);
    const float s = 0.70710678118654752f;
    const float2 w1 = make_float2(s, (SIGN < 0) ? -s : s);
    const float2 w2 = make_float2(0.f, (SIGN < 0) ? -1.f : 1.f);
    const float2 w3 = make_float2(-s, (SIGN < 0) ? -s : s);
    float2 a;
    a = O0;           x[0] = cadd(E0, a); x[4] = csub(E0, a);
    a = cmul(w1, O1); x[1] = cadd(E1, a); x[5] = csub(E1, a);
    a = cmul(w2, O2); x[2] = cadd(E2, a); x[6] = csub(E2, a);
    a = cmul(w3, O3); x[3] = cadd(E3, a); x[7] = csub(E3, a);
}

__device__ __forceinline__ void rfft8(float4 r0, float4 r1, float2 out[5]) {
    float e0 = r0.x, e1 = r0.z, e2 = r1.x, e3 = r1.z;
    float o0 = r0.y, o1 = r0.w, o2 = r1.y, o3 = r1.w;
    float ep = e0 + e2, em = e0 - e2, eq = e1 + e3, er = e1 - e3;
    float op = o0 + o2, om = o0 - o2, oq = o1 + o3, orr = o1 - o3;
    float E0 = ep + eq, E2 = ep - eq;
    float O0 = op + oq, O2 = op - oq;
    const float s = 0.70710678118654752f;
    float w1x = s * (om - orr), w1y = s * (-orr - om);
    float w3x = s * (orr - om), w3y = -s * (om + orr);
    out[0] = make_float2(E0 + O0, 0.f);
    out[1] = make_float2(em + w1x, -er + w1y);
    out[2] = make_float2(E2, -O2);
    out[3] = make_float2(em + w3x, er + w3y);
    out[4] = make_float2(E0 - O0, 0.f);
}

__global__ void __launch_bounds__(256, 3) fftk(const float* __restrict__ Wr,
                                               const float* __restrict__ Wi,
                                               const float* __restrict__ csc) {
    const int bc = blockIdx.y;
    const int b = bc / HIDDEN, c = bc % HIDDEN;
    __shared__ float2 S[PP * PF];
    const int t = threadIdx.x;
    if (t < PP * PF) {
        int ky = t / PF, kx = t % PF;
        float mask = expf(-(float)(ky * ky + kx * kx) * (1.f / 18.f));
        float boost = 1.f + mask * (csc[c] * (0.5f + g_mod[b]));
        float sc = boost * (1.f / 64.f);
        S[t] = make_float2(Wr[c * 40 + t] * sc, Wi[c * 40 + t] * sc);
    }
    __syncthreads();

    const int p = blockIdx.x * 256 + t;
    float* base = g_feat + (((size_t)bc) << 16) + (p >> 5) * (PP * WIDTH) + (p & 31) * PP;

    float2 F[5][8];
#pragma unroll
    for (int y = 0; y < 8; y++) {
        float4 r0 = *(const float4*)(base + y * WIDTH);
        float4 r1 = *(const float4*)(base + y * WIDTH + 4);
        float2 o5[5];
        rfft8(r0, r1, o5);
#pragma unroll
        for (int k = 0; k < 5; k++) F[k][y] = o5[k];
    }
#pragma unroll
    for (int k = 0; k < 5; k++) cfft8<-1>(F[k]);
#pragma unroll
    for (int k = 0; k < 5; k++)
#pragma unroll
        for (int ky = 0; ky < 8; ky++)
            F[k][ky] = cmul(F[k][ky], S[ky * PF + k]);
#pragma unroll
    for (int k = 0; k < 5; k++) cfft8<1>(F[k]);
#pragma unroll
    for (int y = 0; y < 8; y++) {
        float2 z[8];
        z[0] = make_float2(F[0][y].x, 0.f);
        z[1] = F[1][y]; z[2] = F[2][y]; z[3] = F[3][y];
        z[4] = make_float2(F[4][y].x, 0.f);
        z[5] = make_float2(F[3][y].x, -F[3][y].y);
        z[6] = make_float2(F[2][y].x, -F[2][y].y);
        z[7] = make_float2(F[1][y].x, -F[1][y].y);
        cfft8<1>(z);
        *(float4*)(base + y * WIDTH)     = make_float4(z[0].x, z[1].x, z[2].x, z[3].x);
        *(float4*)(base + y * WIDTH + 4) = make_float4(z[4].x, z[5].x, z[6].x, z[7].x);
    }
}

// ================= launch =================
extern "C" void kernel_launch(void* const* d_in, const int* in_sizes, int n_in,
                              void* d_out, int out_size) {
    const float* x     = (const float*)d_in[0];
    const float* w_in  = (const float*)d_in[1];
    const float* w_dw  = (const float*)d_in[2];
    const float* w_out = (const float*)d_in[3];
    const float* Wr    = (const float*)d_in[4];
    const float* Wi    = (const float*)d_in[5];
    const float* csc   = (const float*)d_in[6];
    const float* wm1   = (const float*)d_in[7];
    const float* wm2   = (const float*)d_in[8];
    float* out = (float*)d_out;

    cudaFuncSetAttribute(gemm1_tc, cudaFuncAttributeMaxDynamicSharedMemorySize, 98304);
    cudaFuncSetAttribute(gemm2_tc, cudaFuncAttributeMaxDynamicSharedMemorySize, 110592);

    wsplit<<<96, 256>>>(w_in, w_out);
    noop<<<1, 32>>>();
    noop<<<1, 32>>>();
    gemm1_tc<<<dim3(512, BATCH), 256, 98304>>>(x);          // launch index 3 -> ncu window
    dwk<<<dim3(2, 8, BATCH * HIDDEN), 256>>>(w_dw);
    modk<<<BATCH, 256>>>(wm1, wm2);
    fftk<<<dim3(4, BATCH * HIDDEN), 256>>>(Wr, Wi, csc);
    gemm2_tc<<<dim3(512, BATCH), 256, 110592>>>(out);
}